// round 10
// baseline (speedup 1.0000x reference)
#include <cuda_runtime.h>
#include <cuda_bf16.h>
#include <math.h>
#include <stdint.h>

// Problem constants
#define B_    4
#define S_    1024
#define HID_  4096
#define NH_   32
#define NKV_  8
#define HD_   128
#define NNZ_  (B_ * S_)

// ---------------------------------------------------------------------------
// Scratch (static device allocations; runtime alloc is forbidden)
// ---------------------------------------------------------------------------
__device__ float g_q[(size_t)NNZ_ * NH_ * HD_];     // fp32 proj outputs
__device__ float g_k[(size_t)NNZ_ * NKV_ * HD_];
__device__ float g_v[(size_t)NNZ_ * NKV_ * HD_];

// bf16 split planes (hi/lo)
__device__ __nv_bfloat16 g_hs_h[(size_t)NNZ_ * HID_];
__device__ __nv_bfloat16 g_hs_l[(size_t)NNZ_ * HID_];
__device__ __nv_bfloat16 g_wq_h[(size_t)(NH_ * HD_) * HID_];
__device__ __nv_bfloat16 g_wq_l[(size_t)(NH_ * HD_) * HID_];
__device__ __nv_bfloat16 g_wk_h[(size_t)(NKV_ * HD_) * HID_];
__device__ __nv_bfloat16 g_wk_l[(size_t)(NKV_ * HD_) * HID_];
__device__ __nv_bfloat16 g_wv_h[(size_t)(NKV_ * HD_) * HID_];
__device__ __nv_bfloat16 g_wv_l[(size_t)(NKV_ * HD_) * HID_];
__device__ __nv_bfloat16 g_wo_h[(size_t)HID_ * (NH_ * HD_)];
__device__ __nv_bfloat16 g_wo_l[(size_t)HID_ * (NH_ * HD_)];
__device__ __nv_bfloat16 g_at_h[(size_t)NNZ_ * (NH_ * HD_)];   // FA output planes
__device__ __nv_bfloat16 g_at_l[(size_t)NNZ_ * (NH_ * HD_)];

// roped/scaled Q,K and transposed V planes for tensor-core FA
__device__ __nv_bfloat16 g_qh[(size_t)NNZ_ * NH_ * HD_];
__device__ __nv_bfloat16 g_ql[(size_t)NNZ_ * NH_ * HD_];
__device__ __nv_bfloat16 g_kh[(size_t)NNZ_ * NKV_ * HD_];
__device__ __nv_bfloat16 g_kl[(size_t)NNZ_ * NKV_ * HD_];
__device__ __nv_bfloat16 g_vth[(size_t)B_ * NKV_ * HD_ * S_];  // [b][hk][d][s]
__device__ __nv_bfloat16 g_vtl[(size_t)B_ * NKV_ * HD_ * S_];

// ---------------------------------------------------------------------------
// PTX helpers — sm_80-compatible vocabulary ONLY (harness PTX targets
// compute_103 without the 'a' suffix, so tcgen05/TMA are unavailable).
// ---------------------------------------------------------------------------
__device__ __forceinline__ uint32_t s2u(const void* p) {
    uint32_t a;
    asm("{ .reg .u64 t; cvta.to.shared.u64 t, %1; cvt.u32.u64 %0, t; }"
        : "=r"(a) : "l"(p));
    return a;
}

__device__ __forceinline__ void cp16(uint32_t s, const void* g) {
    asm volatile("cp.async.cg.shared.global [%0], [%1], 16;" :: "r"(s), "l"(g));
}
#define CP_COMMIT() asm volatile("cp.async.commit_group;" ::: "memory")
#define CP_WAIT(n)  asm volatile("cp.async.wait_group %0;" :: "n"(n) : "memory")

__device__ __forceinline__ void ldm_x4(uint32_t* r, uint32_t addr) {
    asm volatile("ldmatrix.sync.aligned.m8n8.x4.shared.b16 {%0,%1,%2,%3}, [%4];"
                 : "=r"(r[0]), "=r"(r[1]), "=r"(r[2]), "=r"(r[3]) : "r"(addr));
}

__device__ __forceinline__ void mma16816(float* d, const uint32_t* a,
                                         const uint32_t* b) {
    asm volatile(
        "mma.sync.aligned.m16n8k16.row.col.f32.bf16.bf16.f32 "
        "{%0,%1,%2,%3}, {%4,%5,%6,%7}, {%8,%9}, {%0,%1,%2,%3};"
        : "+f"(d[0]), "+f"(d[1]), "+f"(d[2]), "+f"(d[3])
        : "r"(a[0]), "r"(a[1]), "r"(a[2]), "r"(a[3]), "r"(b[0]), "r"(b[1]));
}

__device__ __forceinline__ uint32_t packbf2(float lo, float hi) {
    __nv_bfloat162 t = __floats2bfloat162_rn(lo, hi);   // .x=lo (low 16 bits)
    return *reinterpret_cast<uint32_t*>(&t);
}

// ---------------------------------------------------------------------------
// Split fp32 -> (bf16 hi, bf16 lo) planes.
// ---------------------------------------------------------------------------
__global__ void split_fp32_bf16(const float* __restrict__ src,
                                __nv_bfloat16* __restrict__ hi,
                                __nv_bfloat16* __restrict__ lo) {
    size_t i = (size_t)blockIdx.x * blockDim.x + threadIdx.x;
    float4 v = ((const float4*)src)[i];
    float x[4] = {v.x, v.y, v.z, v.w};
    union { __nv_bfloat16 b[4]; ushort4 u; } H, L;
#pragma unroll
    for (int j = 0; j < 4; ++j) {
        H.b[j] = __float2bfloat16(x[j]);
        L.b[j] = __float2bfloat16(x[j] - __bfloat162float(H.b[j]));
    }
    ((ushort4*)hi)[i] = H.u;
    ((ushort4*)lo)[i] = L.u;
}

// ---------------------------------------------------------------------------
// bf16-split GEMM via mma.sync (unchanged from R9 — pinned at the legacy
// HMMA pipe rate ~270 TF/s effective; tile shape no longer matters).
// ---------------------------------------------------------------------------
#define A_PLANE   8192
#define B_PLANE   16384
#define STAGE_B   (2 * A_PLANE + 2 * B_PLANE)
#define G_SMEM    (3 * STAGE_B)

__global__ __launch_bounds__(256, 1)
void gemm_mma_split(const __nv_bfloat16* __restrict__ Ah,
                    const __nv_bfloat16* __restrict__ Al,
                    const __nv_bfloat16* __restrict__ Bh,
                    const __nv_bfloat16* __restrict__ Bl,
                    float* __restrict__ C, int N, int K) {
    extern __shared__ char smc[];
    const uint32_t sb = s2u(smc);
    const int tid  = threadIdx.x;
    const int wid  = tid >> 5, lane = tid & 31;
    const int wm   = wid >> 2, wn = wid & 3;
    const int m0   = blockIdx.y * 128, n0 = blockIdx.x * 256;

    const int lrow = tid >> 1;
    const int cg0  = (tid & 1) * 2;
    const __nv_bfloat16* gAh = Ah + (size_t)(m0 + lrow) * K + cg0 * 8;
    const __nv_bfloat16* gAl = Al + (size_t)(m0 + lrow) * K + cg0 * 8;
    const __nv_bfloat16* gBh = Bh + (size_t)(n0 + lrow) * K + cg0 * 8;
    const __nv_bfloat16* gBl = Bl + (size_t)(n0 + lrow) * K + cg0 * 8;
    const size_t rowskip = (size_t)128 * K;
    const int swl = (lrow >> 1) & 3;
    uint32_t soff[2];
    soff[0] = lrow * 64 + (((cg0 + 0) ^ swl) << 4);
    soff[1] = lrow * 64 + (((cg0 + 1) ^ swl) << 4);

#define LOAD_CHUNK(kt, st) do {                                           \
        uint32_t b_ = sb + (st) * STAGE_B;                                \
        size_t  g_ = (size_t)(kt) * 32;                                   \
        cp16(b_ + soff[0],                      gAh + g_);                \
        cp16(b_ + soff[1],                      gAh + g_ + 8);            \
        cp16(b_ + A_PLANE + soff[0],            gAl + g_);                \
        cp16(b_ + A_PLANE + soff[1],            gAl + g_ + 8);            \
        cp16(b_ + 2 * A_PLANE + soff[0],        gBh + g_);                \
        cp16(b_ + 2 * A_PLANE + soff[1],        gBh + g_ + 8);            \
        cp16(b_ + 2 * A_PLANE + 8192 + soff[0], gBh + g_ + rowskip);      \
        cp16(b_ + 2 * A_PLANE + 8192 + soff[1], gBh + g_ + rowskip + 8);  \
        cp16(b_ + 2 * A_PLANE + B_PLANE + soff[0],        gBl + g_);      \
        cp16(b_ + 2 * A_PLANE + B_PLANE + soff[1],        gBl + g_ + 8);  \
        cp16(b_ + 2 * A_PLANE + B_PLANE + 8192 + soff[0], gBl + g_ + rowskip);     \
        cp16(b_ + 2 * A_PLANE + B_PLANE + 8192 + soff[1], gBl + g_ + rowskip + 8); \
        CP_COMMIT();                                                      \
    } while (0)

    uint32_t aoff[4][2];
#pragma unroll
    for (int t = 0; t < 4; ++t) {
        int row = wm * 64 + t * 16 + (lane & 15);
        int sw  = (row >> 1) & 3;
#pragma unroll
        for (int h = 0; h < 2; ++h) {
            int cg = 2 * h + (lane >> 4);
            aoff[t][h] = row * 64 + ((cg ^ sw) << 4);
        }
    }
    uint32_t boff[4][2];
#pragma unroll
    for (int j = 0; j < 4; ++j) {
        int row = wn * 64 + j * 16 + ((lane >> 4) << 3) + (lane & 7);
        int sw  = (row >> 1) & 3;
#pragma unroll
        for (int h = 0; h < 2; ++h) {
            int cg = 2 * h + ((lane >> 3) & 1);
            boff[j][h] = row * 64 + ((cg ^ sw) << 4);
        }
    }

    float acc[4][8][4];
#pragma unroll
    for (int t = 0; t < 4; ++t)
#pragma unroll
        for (int n = 0; n < 8; ++n)
#pragma unroll
            for (int e = 0; e < 4; ++e) acc[t][n][e] = 0.0f;

    const int nkt = K >> 5;
    LOAD_CHUNK(0, 0);
    LOAD_CHUNK(1, 1);

    for (int kt = 0; kt < nkt; ++kt) {
        const int s = kt % 3;
        if (kt + 1 < nkt) { CP_WAIT(1); } else { CP_WAIT(0); }
        __syncthreads();
        if (kt + 2 < nkt) LOAD_CHUNK(kt + 2, (kt + 2) % 3);

        const uint32_t pA_h = sb + s * STAGE_B;
        const uint32_t pA_l = pA_h + A_PLANE;
        const uint32_t pB_h = pA_h + 2 * A_PLANE;
        const uint32_t pB_l = pB_h + B_PLANE;

#pragma unroll
        for (int h = 0; h < 2; ++h) {
            uint32_t ah[4][4], al[4][4], bh[4][4], bl[4][4];
#pragma unroll
            for (int t = 0; t < 4; ++t) {
                ldm_x4(ah[t], pA_h + aoff[t][h]);
                ldm_x4(al[t], pA_l + aoff[t][h]);
            }
#pragma unroll
            for (int j = 0; j < 4; ++j) {
                ldm_x4(bh[j], pB_h + boff[j][h]);
                ldm_x4(bl[j], pB_l + boff[j][h]);
            }
#pragma unroll
            for (int t = 0; t < 4; ++t)
#pragma unroll
                for (int j = 0; j < 4; ++j) {
                    mma16816(acc[t][2 * j],     ah[t], &bh[j][0]);
                    mma16816(acc[t][2 * j + 1], ah[t], &bh[j][2]);
                    mma16816(acc[t][2 * j],     ah[t], &bl[j][0]);
                    mma16816(acc[t][2 * j + 1], ah[t], &bl[j][2]);
                    mma16816(acc[t][2 * j],     al[t], &bh[j][0]);
                    mma16816(acc[t][2 * j + 1], al[t], &bh[j][2]);
                }
        }
    }

    float* Cw = C + (size_t)(m0 + wm * 64) * N + n0 + wn * 64;
#pragma unroll
    for (int t = 0; t < 4; ++t)
#pragma unroll
        for (int n = 0; n < 8; ++n) {
            int r = t * 16 + (lane >> 2);
            int c = n * 8 + (lane & 3) * 2;
            *(float2*)&Cw[(size_t)r * N + c] =
                make_float2(acc[t][n][0], acc[t][n][1]);
            *(float2*)&Cw[(size_t)(r + 8) * N + c] =
                make_float2(acc[t][n][2], acc[t][n][3]);
        }
#undef LOAD_CHUNK
}

// ---------------------------------------------------------------------------
// RoPE + bf16 split. grid (NNZ, 40): y<32 -> Q head (scaled), else K head.
// ---------------------------------------------------------------------------
__global__ void rope_split(const int* __restrict__ pos_ids) {
    const int tok = blockIdx.x;
    const int hh  = blockIdx.y;
    const int d   = threadIdx.x;               // 0..63
    const float p = (float)pos_ids[tok];

    float fr = (float)pow(500000.0, -(double)d / 64.0);
    const float two_pi = 6.283185307179586f;
    float wav = two_pi / fr;
    float f;
    if (wav < 2048.0f)       f = fr;
    else if (wav > 8192.0f)  f = fr * 0.125f;
    else {
        float smooth = (8192.0f / wav - 1.0f) * (1.0f / 3.0f);
        f = (1.0f - smooth) * fr * 0.125f + smooth * fr;
    }
    float ang = p * f;
    float c = cosf(ang), s = sinf(ang);

    if (hh < NH_) {
        const float sc = 0.08838834764831845f;   // 1/sqrt(128) folded into Q
        size_t base = (size_t)tok * (NH_ * HD_) + hh * HD_ + d;
        float x1 = g_q[base], x2 = g_q[base + 64];
        float y1 = (x1 * c - x2 * s) * sc;
        float y2 = (x2 * c + x1 * s) * sc;
        __nv_bfloat16 h1 = __float2bfloat16(y1);
        __nv_bfloat16 h2 = __float2bfloat16(y2);
        g_qh[base]      = h1; g_ql[base]      = __float2bfloat16(y1 - __bfloat162float(h1));
        g_qh[base + 64] = h2; g_ql[base + 64] = __float2bfloat16(y2 - __bfloat162float(h2));
    } else {
        int hk = hh - NH_;
        size_t base = (size_t)tok * (NKV_ * HD_) + hk * HD_ + d;
        float x1 = g_k[base], x2 = g_k[base + 64];
        float y1 = x1 * c - x2 * s;
        float y2 = x2 * c + x1 * s;
        __nv_bfloat16 h1 = __float2bfloat16(y1);
        __nv_bfloat16 h2 = __float2bfloat16(y2);
        g_kh[base]      = h1; g_kl[base]      = __float2bfloat16(y1 - __bfloat162float(h1));
        g_kh[base + 64] = h2; g_kl[base + 64] = __float2bfloat16(y2 - __bfloat162float(h2));
    }
}

// ---------------------------------------------------------------------------
// V transpose + split: g_v [tok][hk][d] fp32 -> g_vth/g_vtl [b][hk][d][s] bf16.
// grid (32 bhk, 32 s-tiles, 4 d-tiles), block (32,8), smem 32x33 transpose.
// ---------------------------------------------------------------------------
__global__ void v_split_t() {
    __shared__ float t[32][33];
    const int bhk = blockIdx.x, st = blockIdx.y, dt = blockIdx.z;
    const int b = bhk >> 3, hk = bhk & 7;
    const int tx = threadIdx.x, ty = threadIdx.y;
#pragma unroll
    for (int i = 0; i < 4; ++i) {
        int s = ty + 8 * i;
        t[s][tx] = g_v[(size_t)(b * S_ + st * 32 + s) * (NKV_ * HD_)
                       + hk * HD_ + dt * 32 + tx];
    }
    __syncthreads();
#pragma unroll
    for (int i = 0; i < 4; ++i) {
        int d = ty + 8 * i;
        float v = t[tx][d];
        __nv_bfloat16 h = __float2bfloat16(v);
        size_t idx = (size_t)(bhk * HD_ + dt * 32 + d) * S_ + st * 32 + tx;
        g_vth[idx] = h;
        g_vtl[idx] = __float2bfloat16(v - __bfloat162float(h));
    }
}

// ---------------------------------------------------------------------------
// Tensor-core flash attention (causal, GQA 4:1), 3-term bf16 splits on both
// QK^T and PV. Block = (qtile 128 rows, head, batch); 8 warps x 16 q-rows.
// Key tiles of 64, double-buffered cp.async.
// smem: QH 32K | QL 32K | 2 stages x (KH 16K | KL 16K | VH 16K | VL 16K).
// Per-plane layout: [32-elem d/key chunks][rows][32] with the 64B-row swizzle.
// ---------------------------------------------------------------------------
#define FA_SMEM (65536 + 2 * 65536)

__global__ __launch_bounds__(256, 1)
void fa_mma() {
    extern __shared__ char smf[];
    const uint32_t sb = s2u(smf);
    const int qt   = blockIdx.x;               // 0..7 (q-tile of 128)
    const int head = blockIdx.y;
    const int b    = blockIdx.z;
    const int hk   = head >> 2;
    const int bhk  = b * NKV_ + hk;
    const int tid  = threadIdx.x;
    const int wid  = tid >> 5, lane = tid & 31;
    const int tok0 = b * S_ + qt * 128;
    const int nt   = 2 * (qt + 1);             // key tiles of 64

#define FA_LOAD_KV(jt_, st_) do {                                          \
        uint32_t kb_ = sb + 65536 + (st_) * 65536;                         \
        int tokb_ = b * S_ + (jt_) * 64;                                   \
        _Pragma("unroll")                                                  \
        for (int i_ = 0; i_ < 4; ++i_) {                                   \
            int cid_ = tid + 256 * i_;                                     \
            int kr_ = cid_ >> 4, c16_ = cid_ & 15;                         \
            uint32_t so_ = (uint32_t)((c16_ >> 2) * 4096 + kr_ * 64 +      \
                            ((((c16_ & 3) ^ ((kr_ >> 1) & 3))) << 4));     \
            size_t gi_ = (size_t)(tokb_ + kr_) * (NKV_ * HD_)              \
                         + hk * HD_ + c16_ * 8;                            \
            cp16(kb_ + so_,         &g_kh[gi_]);                           \
            cp16(kb_ + 16384 + so_, &g_kl[gi_]);                           \
        }                                                                  \
        _Pragma("unroll")                                                  \
        for (int i_ = 0; i_ < 4; ++i_) {                                   \
            int cid_ = tid + 256 * i_;                                     \
            int dr_ = cid_ >> 3, kc_ = cid_ & 7;                           \
            uint32_t so_ = (uint32_t)((kc_ >> 2) * 8192 + dr_ * 64 +       \
                            ((((kc_ & 3) ^ ((dr_ >> 1) & 3))) << 4));      \
            size_t gi_ = (size_t)(bhk * HD_ + dr_) * S_ + (jt_) * 64       \
                         + kc_ * 8;                                        \
            cp16(kb_ + 32768 + so_, &g_vth[gi_]);                          \
            cp16(kb_ + 49152 + so_, &g_vtl[gi_]);                          \
        }                                                                  \
    } while (0)

    // Q tile (once): [128 rows][128 d] both planes
#pragma unroll
    for (int i = 0; i < 8; ++i) {
        int cid = tid + 256 * i;
        int qr = cid >> 4, c16 = cid & 15;
        uint32_t so = (uint32_t)((c16 >> 2) * 8192 + qr * 64 +
                      ((((c16 & 3) ^ ((qr >> 1) & 3))) << 4));
        size_t gi = (size_t)(tok0 + qr) * (NH_ * HD_) + head * HD_ + c16 * 8;
        cp16(sb + so,         &g_qh[gi]);
        cp16(sb + 32768 + so, &g_ql[gi]);
    }
    FA_LOAD_KV(0, 0);
    CP_COMMIT();

    float o[16][4];
#pragma unroll
    for (int n = 0; n < 16; ++n)
#pragma unroll
        for (int e = 0; e < 4; ++e) o[n][e] = 0.0f;
    float m0 = -1e30f, m1 = -1e30f, l0 = 0.0f, l1 = 0.0f;

    const int r0a = qt * 128 + wid * 16 + (lane >> 2);   // abs q row (thread)

    for (int jt = 0; jt < nt; ++jt) {
        CP_WAIT(0);
        __syncthreads();
        if (jt + 1 < nt) { FA_LOAD_KV(jt + 1, (jt + 1) & 1); CP_COMMIT(); }

        const uint32_t kb  = sb + 65536 + (jt & 1) * 65536;
        const uint32_t KHb = kb, KLb = kb + 16384;
        const uint32_t VHb = kb + 32768, VLb = kb + 49152;

        // ---- S = Q K^T (3-term), warp tile [16 x 64] ----
        float sc[8][4];
#pragma unroll
        for (int f = 0; f < 8; ++f)
#pragma unroll
            for (int e = 0; e < 4; ++e) sc[f][e] = 0.0f;

#pragma unroll
        for (int h8 = 0; h8 < 8; ++h8) {
            uint32_t qh_f[4], ql_f[4];
            {
                int row = (wid << 4) + (lane & 15);
                int cg = 2 * (h8 & 1) + (lane >> 4);
                uint32_t off = (uint32_t)((h8 >> 1) * 8192 + row * 64 +
                               ((cg ^ ((row >> 1) & 3)) << 4));
                ldm_x4(qh_f, sb + off);
                ldm_x4(ql_f, sb + 32768 + off);
            }
            uint32_t kh_f[4][4], kl_f[4][4];
#pragma unroll
            for (int j = 0; j < 4; ++j) {
                int row = j * 16 + ((lane >> 4) << 3) + (lane & 7);
                int cg = 2 * (h8 & 1) + ((lane >> 3) & 1);
                uint32_t off = (uint32_t)((h8 >> 1) * 4096 + row * 64 +
                               ((cg ^ ((row >> 1) & 3)) << 4));
                ldm_x4(kh_f[j], KHb + off);
                ldm_x4(kl_f[j], KLb + off);
            }
#pragma unroll
            for (int j = 0; j < 4; ++j) {
                mma16816(sc[2 * j],     qh_f, &kh_f[j][0]);
                mma16816(sc[2 * j + 1], qh_f, &kh_f[j][2]);
                mma16816(sc[2 * j],     qh_f, &kl_f[j][0]);
                mma16816(sc[2 * j + 1], qh_f, &kl_f[j][2]);
                mma16816(sc[2 * j],     ql_f, &kh_f[j][0]);
                mma16816(sc[2 * j + 1], ql_f, &kh_f[j][2]);
            }
        }

        // ---- causal mask (diagonal tiles only) ----
        if (jt >= 2 * qt) {
            int kk0 = jt * 64 + 2 * (lane & 3);
#pragma unroll
            for (int f = 0; f < 8; ++f) {
                int k0 = kk0 + 8 * f;
                if (k0     > r0a)     sc[f][0] = -1e30f;
                if (k0 + 1 > r0a)     sc[f][1] = -1e30f;
                if (k0     > r0a + 8) sc[f][2] = -1e30f;
                if (k0 + 1 > r0a + 8) sc[f][3] = -1e30f;
            }
        }

        // ---- online softmax (rows r0a, r0a+8; 4-lane groups per row) ----
        float t0 = -1e30f, t1 = -1e30f;
#pragma unroll
        for (int f = 0; f < 8; ++f) {
            t0 = fmaxf(t0, fmaxf(sc[f][0], sc[f][1]));
            t1 = fmaxf(t1, fmaxf(sc[f][2], sc[f][3]));
        }
        t0 = fmaxf(t0, __shfl_xor_sync(0xffffffffu, t0, 1));
        t0 = fmaxf(t0, __shfl_xor_sync(0xffffffffu, t0, 2));
        t1 = fmaxf(t1, __shfl_xor_sync(0xffffffffu, t1, 1));
        t1 = fmaxf(t1, __shfl_xor_sync(0xffffffffu, t1, 2));
        float m0n = fmaxf(m0, t0), m1n = fmaxf(m1, t1);
        float c0 = __expf(m0 - m0n), c1 = __expf(m1 - m1n);
        m0 = m0n; m1 = m1n;

        float rs0 = 0.0f, rs1 = 0.0f;
#pragma unroll
        for (int f = 0; f < 8; ++f) {
            sc[f][0] = __expf(sc[f][0] - m0); rs0 += sc[f][0];
            sc[f][1] = __expf(sc[f][1] - m0); rs0 += sc[f][1];
            sc[f][2] = __expf(sc[f][2] - m1); rs1 += sc[f][2];
            sc[f][3] = __expf(sc[f][3] - m1); rs1 += sc[f][3];
        }
        rs0 += __shfl_xor_sync(0xffffffffu, rs0, 1);
        rs0 += __shfl_xor_sync(0xffffffffu, rs0, 2);
        rs1 += __shfl_xor_sync(0xffffffffu, rs1, 1);
        rs1 += __shfl_xor_sync(0xffffffffu, rs1, 2);
        l0 = l0 * c0 + rs0;
        l1 = l1 * c1 + rs1;
#pragma unroll
        for (int n = 0; n < 16; ++n) {
            o[n][0] *= c0; o[n][1] *= c0;
            o[n][2] *= c1; o[n][3] *= c1;
        }

        // ---- pack P into A-fragments (hi + residual lo), in registers ----
        uint32_t pah[4][4], pal[4][4];
#pragma unroll
        for (int kf = 0; kf < 4; ++kf) {
            const int f0 = 2 * kf, f1 = 2 * kf + 1;
            pah[kf][0] = packbf2(sc[f0][0], sc[f0][1]);
            pah[kf][1] = packbf2(sc[f0][2], sc[f0][3]);
            pah[kf][2] = packbf2(sc[f1][0], sc[f1][1]);
            pah[kf][3] = packbf2(sc[f1][2], sc[f1][3]);
            __nv_bfloat162 h0 = *reinterpret_cast<__nv_bfloat162*>(&pah[kf][0]);
            __nv_bfloat162 h1 = *reinterpret_cast<__nv_bfloat162*>(&pah[kf][1]);
            __nv_bfloat162 h2 = *reinterpret_cast<__nv_bfloat162*>(&pah[kf][2]);
            __nv_bfloat162 h3 = *reinterpret_cast<__nv_bfloat162*>(&pah[kf][3]);
            pal[kf][0] = packbf2(sc[f0][0] - __bfloat162float(h0.x),
                                 sc[f0][1] - __bfloat162float(h0.y));
            pal[kf][1] = packbf2(sc[f0][2] - __bfloat162float(h1.x),
                                 sc[f0][3] - __bfloat162float(h1.y));
            pal[kf][2] = packbf2(sc[f1][0] - __bfloat162float(h2.x),
                                 sc[f1][1] - __bfloat162float(h2.y));
            pal[kf][3] = packbf2(sc[f1][2] - __bfloat162float(h3.x),
                                 sc[f1][3] - __bfloat162float(h3.y));
        }

        // ---- O += P V (3-term): warp tile [16 x 128], K = 64 keys ----
#pragma unroll
        for (int j = 0; j < 8; ++j) {
            int row = j * 16 + ((lane >> 4) << 3) + (lane & 7);   // d row
            int swr = (row >> 1) & 3;
#pragma unroll
            for (int kf = 0; kf < 4; ++kf) {
                int cg = 2 * (kf & 1) + ((lane >> 3) & 1);
                uint32_t off = (uint32_t)((kf >> 1) * 8192 + row * 64 +
                               ((cg ^ swr) << 4));
                uint32_t vh_f[4], vl_f[4];
                ldm_x4(vh_f, VHb + off);
                ldm_x4(vl_f, VLb + off);
                mma16816(o[2 * j],     pah[kf], &vh_f[0]);
                mma16816(o[2 * j + 1], pah[kf], &vh_f[2]);
                mma16816(o[2 * j],     pal[kf], &vh_f[0]);
                mma16816(o[2 * j + 1], pal[kf], &vh_f[2]);
                mma16816(o[2 * j],     pah[kf], &vl_f[0]);
                mma16816(o[2 * j + 1], pah[kf], &vl_f[2]);
            }
        }
    }

    // ---- epilogue: normalize, split, write attn hi/lo planes ----
    const float inv0 = 1.0f / l0, inv1 = 1.0f / l1;
    const size_t tr0 = (size_t)(b * S_ + qt * 128 + wid * 16 + (lane >> 2));
#pragma unroll
    for (int n = 0; n < 16; ++n) {
        int d = n * 8 + 2 * (lane & 3);
        {
            float v0 = o[n][0] * inv0, v1 = o[n][1] * inv0;
            uint32_t hp = packbf2(v0, v1);
            __nv_bfloat162 hh = *reinterpret_cast<__nv_bfloat162*>(&hp);
            uint32_t lp = packbf2(v0 - __bfloat162float(hh.x),
                                  v1 - __bfloat162float(hh.y));
            size_t idx = tr0 * (NH_ * HD_) + head * HD_ + d;
            *(uint32_t*)&g_at_h[idx] = hp;
            *(uint32_t*)&g_at_l[idx] = lp;
        }
        {
            float v0 = o[n][2] * inv1, v1 = o[n][3] * inv1;
            uint32_t hp = packbf2(v0, v1);
            __nv_bfloat162 hh = *reinterpret_cast<__nv_bfloat162*>(&hp);
            uint32_t lp = packbf2(v0 - __bfloat162float(hh.x),
                                  v1 - __bfloat162float(hh.y));
            size_t idx = (tr0 + 8) * (NH_ * HD_) + head * HD_ + d;
            *(uint32_t*)&g_at_h[idx] = hp;
            *(uint32_t*)&g_at_l[idx] = lp;
        }
    }
#undef FA_LOAD_KV
}

// ---------------------------------------------------------------------------
// Launch: split -> mma GEMMs (QKV) -> rope_split -> v transpose-split ->
// tensor-core FA -> mma GEMM (O). kv_cache append skipped (identity).
// ---------------------------------------------------------------------------
extern "C" void kernel_launch(void* const* d_in, const int* in_sizes, int n_in,
                              void* d_out, int out_size) {
    const float* hs = (const float*)d_in[0];
    const float* wq = (const float*)d_in[1];
    const float* wk = (const float*)d_in[2];
    const float* wv = (const float*)d_in[3];
    const float* wo = (const float*)d_in[4];
    const int* pos  = (const int*)d_in[6];
    float* out = (float*)d_out;

    float *pq, *pk, *pv;
    cudaGetSymbolAddress((void**)&pq, g_q);
    cudaGetSymbolAddress((void**)&pk, g_k);
    cudaGetSymbolAddress((void**)&pv, g_v);

    __nv_bfloat16 *hsh, *hsl, *wqh, *wql, *wkh, *wkl, *wvh, *wvl, *woh, *wol, *ath, *atl;
    cudaGetSymbolAddress((void**)&hsh, g_hs_h); cudaGetSymbolAddress((void**)&hsl, g_hs_l);
    cudaGetSymbolAddress((void**)&wqh, g_wq_h); cudaGetSymbolAddress((void**)&wql, g_wq_l);
    cudaGetSymbolAddress((void**)&wkh, g_wk_h); cudaGetSymbolAddress((void**)&wkl, g_wk_l);
    cudaGetSymbolAddress((void**)&wvh, g_wv_h); cudaGetSymbolAddress((void**)&wvl, g_wv_l);
    cudaGetSymbolAddress((void**)&woh, g_wo_h); cudaGetSymbolAddress((void**)&wol, g_wo_l);
    cudaGetSymbolAddress((void**)&ath, g_at_h); cudaGetSymbolAddress((void**)&atl, g_at_l);

    cudaFuncSetAttribute(gemm_mma_split, cudaFuncAttributeMaxDynamicSharedMemorySize,
                         G_SMEM);
    cudaFuncSetAttribute(fa_mma, cudaFuncAttributeMaxDynamicSharedMemorySize,
                         FA_SMEM);

    const int BIG4 = (NNZ_ * HID_) / 1024;
    const int SML4 = (NKV_ * HD_ * HID_) / 1024;

    // split inputs/weights to bf16 hi/lo planes
    split_fp32_bf16<<<BIG4, 256>>>(hs, hsh, hsl);
    split_fp32_bf16<<<BIG4, 256>>>(wq, wqh, wql);
    split_fp32_bf16<<<SML4, 256>>>(wk, wkh, wkl);
    split_fp32_bf16<<<SML4, 256>>>(wv, wvh, wvl);
    split_fp32_bf16<<<BIG4, 256>>>(wo, woh, wol);

    // QKV projections (tensor cores via mma.sync)
    gemm_mma_split<<<dim3((NH_ * HD_) / 256, NNZ_ / 128), 256, G_SMEM>>>(
        hsh, hsl, wqh, wql, pq, NH_ * HD_, HID_);
    gemm_mma_split<<<dim3((NKV_ * HD_) / 256, NNZ_ / 128), 256, G_SMEM>>>(
        hsh, hsl, wkh, wkl, pk, NKV_ * HD_, HID_);
    gemm_mma_split<<<dim3((NKV_ * HD_) / 256, NNZ_ / 128), 256, G_SMEM>>>(
        hsh, hsl, wvh, wvl, pv, NKV_ * HD_, HID_);

    // RoPE + split (Q scaled), V transpose + split
    rope_split<<<dim3(NNZ_, NH_ + NKV_), 64>>>(pos);
    v_split_t<<<dim3(B_ * NKV_, S_ / 32, HD_ / 32), dim3(32, 8)>>>();

    // Tensor-core causal GQA flash attention -> attn hi/lo planes
    fa_mma<<<dim3(S_ / 128, NH_, B_), 256, FA_SMEM>>>();

    // O projection
    gemm_mma_split<<<dim3(HID_ / 256, NNZ_ / 128), 256, G_SMEM>>>(
        ath, atl, woh, wol, out, HID_, NH_ * HD_);
}

// round 12
// speedup vs baseline: 1.5802x; 1.5802x over previous
#include <cuda_runtime.h>
#include <cuda_bf16.h>
#include <math.h>
#include <stdint.h>

// Problem constants
#define B_    4
#define S_    1024
#define HID_  4096
#define NH_   32
#define NKV_  8
#define HD_   128
#define NNZ_  (B_ * S_)

// ---------------------------------------------------------------------------
// Scratch (static device allocations; runtime alloc is forbidden)
// ---------------------------------------------------------------------------
__device__ float g_q[(size_t)NNZ_ * NH_ * HD_];     // fp32 proj outputs
__device__ float g_k[(size_t)NNZ_ * NKV_ * HD_];
__device__ float g_v[(size_t)NNZ_ * NKV_ * HD_];

// bf16 split planes (hi/lo)
__device__ __nv_bfloat16 g_hs_h[(size_t)NNZ_ * HID_];
__device__ __nv_bfloat16 g_hs_l[(size_t)NNZ_ * HID_];
__device__ __nv_bfloat16 g_wq_h[(size_t)(NH_ * HD_) * HID_];
__device__ __nv_bfloat16 g_wq_l[(size_t)(NH_ * HD_) * HID_];
__device__ __nv_bfloat16 g_wk_h[(size_t)(NKV_ * HD_) * HID_];
__device__ __nv_bfloat16 g_wk_l[(size_t)(NKV_ * HD_) * HID_];
__device__ __nv_bfloat16 g_wv_h[(size_t)(NKV_ * HD_) * HID_];
__device__ __nv_bfloat16 g_wv_l[(size_t)(NKV_ * HD_) * HID_];
__device__ __nv_bfloat16 g_wo_h[(size_t)HID_ * (NH_ * HD_)];
__device__ __nv_bfloat16 g_wo_l[(size_t)HID_ * (NH_ * HD_)];
__device__ __nv_bfloat16 g_at_h[(size_t)NNZ_ * (NH_ * HD_)];   // FA output planes
__device__ __nv_bfloat16 g_at_l[(size_t)NNZ_ * (NH_ * HD_)];

// roped/scaled Q,K and transposed V planes for tensor-core FA
__device__ __nv_bfloat16 g_qh[(size_t)NNZ_ * NH_ * HD_];
__device__ __nv_bfloat16 g_ql[(size_t)NNZ_ * NH_ * HD_];
__device__ __nv_bfloat16 g_kh[(size_t)NNZ_ * NKV_ * HD_];
__device__ __nv_bfloat16 g_kl[(size_t)NNZ_ * NKV_ * HD_];
__device__ __nv_bfloat16 g_vth[(size_t)B_ * NKV_ * HD_ * S_];  // [b][hk][d][s]
__device__ __nv_bfloat16 g_vtl[(size_t)B_ * NKV_ * HD_ * S_];

// ---------------------------------------------------------------------------
// PTX helpers — sm_80-compatible vocabulary ONLY (harness PTX targets
// compute_103 without the 'a' suffix, so tcgen05/TMA are unavailable).
// ---------------------------------------------------------------------------
__device__ __forceinline__ uint32_t s2u(const void* p) {
    uint32_t a;
    asm("{ .reg .u64 t; cvta.to.shared.u64 t, %1; cvt.u32.u64 %0, t; }"
        : "=r"(a) : "l"(p));
    return a;
}

__device__ __forceinline__ void cp16(uint32_t s, const void* g) {
    asm volatile("cp.async.cg.shared.global [%0], [%1], 16;" :: "r"(s), "l"(g));
}
#define CP_COMMIT() asm volatile("cp.async.commit_group;" ::: "memory")
#define CP_WAIT(n)  asm volatile("cp.async.wait_group %0;" :: "n"(n) : "memory")

__device__ __forceinline__ void ldm_x4(uint32_t* r, uint32_t addr) {
    asm volatile("ldmatrix.sync.aligned.m8n8.x4.shared.b16 {%0,%1,%2,%3}, [%4];"
                 : "=r"(r[0]), "=r"(r[1]), "=r"(r[2]), "=r"(r[3]) : "r"(addr));
}

__device__ __forceinline__ void mma16816(float* d, const uint32_t* a,
                                         const uint32_t* b) {
    asm volatile(
        "mma.sync.aligned.m16n8k16.row.col.f32.bf16.bf16.f32 "
        "{%0,%1,%2,%3}, {%4,%5,%6,%7}, {%8,%9}, {%0,%1,%2,%3};"
        : "+f"(d[0]), "+f"(d[1]), "+f"(d[2]), "+f"(d[3])
        : "r"(a[0]), "r"(a[1]), "r"(a[2]), "r"(a[3]), "r"(b[0]), "r"(b[1]));
}

__device__ __forceinline__ uint32_t packbf2(float lo, float hi) {
    __nv_bfloat162 t = __floats2bfloat162_rn(lo, hi);   // .x=lo (low 16 bits)
    return *reinterpret_cast<uint32_t*>(&t);
}

// ---------------------------------------------------------------------------
// Split fp32 -> (bf16 hi, bf16 lo) planes.
// ---------------------------------------------------------------------------
__global__ void split_fp32_bf16(const float* __restrict__ src,
                                __nv_bfloat16* __restrict__ hi,
                                __nv_bfloat16* __restrict__ lo) {
    size_t i = (size_t)blockIdx.x * blockDim.x + threadIdx.x;
    float4 v = ((const float4*)src)[i];
    float x[4] = {v.x, v.y, v.z, v.w};
    union { __nv_bfloat16 b[4]; ushort4 u; } H, L;
#pragma unroll
    for (int j = 0; j < 4; ++j) {
        H.b[j] = __float2bfloat16(x[j]);
        L.b[j] = __float2bfloat16(x[j] - __bfloat162float(H.b[j]));
    }
    ((ushort4*)hi)[i] = H.u;
    ((ushort4*)lo)[i] = L.u;
}

// ---------------------------------------------------------------------------
// bf16-split GEMM via mma.sync (unchanged — pinned at legacy HMMA pipe rate).
// ---------------------------------------------------------------------------
#define A_PLANE   8192
#define B_PLANE   16384
#define STAGE_B   (2 * A_PLANE + 2 * B_PLANE)
#define G_SMEM    (3 * STAGE_B)

__global__ __launch_bounds__(256, 1)
void gemm_mma_split(const __nv_bfloat16* __restrict__ Ah,
                    const __nv_bfloat16* __restrict__ Al,
                    const __nv_bfloat16* __restrict__ Bh,
                    const __nv_bfloat16* __restrict__ Bl,
                    float* __restrict__ C, int N, int K) {
    extern __shared__ char smc[];
    const uint32_t sb = s2u(smc);
    const int tid  = threadIdx.x;
    const int wid  = tid >> 5, lane = tid & 31;
    const int wm   = wid >> 2, wn = wid & 3;
    const int m0   = blockIdx.y * 128, n0 = blockIdx.x * 256;

    const int lrow = tid >> 1;
    const int cg0  = (tid & 1) * 2;
    const __nv_bfloat16* gAh = Ah + (size_t)(m0 + lrow) * K + cg0 * 8;
    const __nv_bfloat16* gAl = Al + (size_t)(m0 + lrow) * K + cg0 * 8;
    const __nv_bfloat16* gBh = Bh + (size_t)(n0 + lrow) * K + cg0 * 8;
    const __nv_bfloat16* gBl = Bl + (size_t)(n0 + lrow) * K + cg0 * 8;
    const size_t rowskip = (size_t)128 * K;
    const int swl = (lrow >> 1) & 3;
    uint32_t soff[2];
    soff[0] = lrow * 64 + (((cg0 + 0) ^ swl) << 4);
    soff[1] = lrow * 64 + (((cg0 + 1) ^ swl) << 4);

#define LOAD_CHUNK(kt, st) do {                                           \
        uint32_t b_ = sb + (st) * STAGE_B;                                \
        size_t  g_ = (size_t)(kt) * 32;                                   \
        cp16(b_ + soff[0],                      gAh + g_);                \
        cp16(b_ + soff[1],                      gAh + g_ + 8);            \
        cp16(b_ + A_PLANE + soff[0],            gAl + g_);                \
        cp16(b_ + A_PLANE + soff[1],            gAl + g_ + 8);            \
        cp16(b_ + 2 * A_PLANE + soff[0],        gBh + g_);                \
        cp16(b_ + 2 * A_PLANE + soff[1],        gBh + g_ + 8);            \
        cp16(b_ + 2 * A_PLANE + 8192 + soff[0], gBh + g_ + rowskip);      \
        cp16(b_ + 2 * A_PLANE + 8192 + soff[1], gBh + g_ + rowskip + 8);  \
        cp16(b_ + 2 * A_PLANE + B_PLANE + soff[0],        gBl + g_);      \
        cp16(b_ + 2 * A_PLANE + B_PLANE + soff[1],        gBl + g_ + 8);  \
        cp16(b_ + 2 * A_PLANE + B_PLANE + 8192 + soff[0], gBl + g_ + rowskip);     \
        cp16(b_ + 2 * A_PLANE + B_PLANE + 8192 + soff[1], gBl + g_ + rowskip + 8); \
        CP_COMMIT();                                                      \
    } while (0)

    uint32_t aoff[4][2];
#pragma unroll
    for (int t = 0; t < 4; ++t) {
        int row = wm * 64 + t * 16 + (lane & 15);
        int sw  = (row >> 1) & 3;
#pragma unroll
        for (int h = 0; h < 2; ++h) {
            int cg = 2 * h + (lane >> 4);
            aoff[t][h] = row * 64 + ((cg ^ sw) << 4);
        }
    }
    uint32_t boff[4][2];
#pragma unroll
    for (int j = 0; j < 4; ++j) {
        int row = wn * 64 + j * 16 + ((lane >> 4) << 3) + (lane & 7);
        int sw  = (row >> 1) & 3;
#pragma unroll
        for (int h = 0; h < 2; ++h) {
            int cg = 2 * h + ((lane >> 3) & 1);
            boff[j][h] = row * 64 + ((cg ^ sw) << 4);
        }
    }

    float acc[4][8][4];
#pragma unroll
    for (int t = 0; t < 4; ++t)
#pragma unroll
        for (int n = 0; n < 8; ++n)
#pragma unroll
            for (int e = 0; e < 4; ++e) acc[t][n][e] = 0.0f;

    const int nkt = K >> 5;
    LOAD_CHUNK(0, 0);
    LOAD_CHUNK(1, 1);

    for (int kt = 0; kt < nkt; ++kt) {
        const int s = kt % 3;
        if (kt + 1 < nkt) { CP_WAIT(1); } else { CP_WAIT(0); }
        __syncthreads();
        if (kt + 2 < nkt) LOAD_CHUNK(kt + 2, (kt + 2) % 3);

        const uint32_t pA_h = sb + s * STAGE_B;
        const uint32_t pA_l = pA_h + A_PLANE;
        const uint32_t pB_h = pA_h + 2 * A_PLANE;
        const uint32_t pB_l = pB_h + B_PLANE;

#pragma unroll
        for (int h = 0; h < 2; ++h) {
            uint32_t ah[4][4], al[4][4], bh[4][4], bl[4][4];
#pragma unroll
            for (int t = 0; t < 4; ++t) {
                ldm_x4(ah[t], pA_h + aoff[t][h]);
                ldm_x4(al[t], pA_l + aoff[t][h]);
            }
#pragma unroll
            for (int j = 0; j < 4; ++j) {
                ldm_x4(bh[j], pB_h + boff[j][h]);
                ldm_x4(bl[j], pB_l + boff[j][h]);
            }
#pragma unroll
            for (int t = 0; t < 4; ++t)
#pragma unroll
                for (int j = 0; j < 4; ++j) {
                    mma16816(acc[t][2 * j],     ah[t], &bh[j][0]);
                    mma16816(acc[t][2 * j + 1], ah[t], &bh[j][2]);
                    mma16816(acc[t][2 * j],     ah[t], &bl[j][0]);
                    mma16816(acc[t][2 * j + 1], ah[t], &bl[j][2]);
                    mma16816(acc[t][2 * j],     al[t], &bh[j][0]);
                    mma16816(acc[t][2 * j + 1], al[t], &bh[j][2]);
                }
        }
    }

    float* Cw = C + (size_t)(m0 + wm * 64) * N + n0 + wn * 64;
#pragma unroll
    for (int t = 0; t < 4; ++t)
#pragma unroll
        for (int n = 0; n < 8; ++n) {
            int r = t * 16 + (lane >> 2);
            int c = n * 8 + (lane & 3) * 2;
            *(float2*)&Cw[(size_t)r * N + c] =
                make_float2(acc[t][n][0], acc[t][n][1]);
            *(float2*)&Cw[(size_t)(r + 8) * N + c] =
                make_float2(acc[t][n][2], acc[t][n][3]);
        }
#undef LOAD_CHUNK
}

// ---------------------------------------------------------------------------
// RoPE + bf16 split. grid (NNZ, 40): y<32 -> Q head (scaled), else K head.
// ---------------------------------------------------------------------------
__global__ void rope_split(const int* __restrict__ pos_ids) {
    const int tok = blockIdx.x;
    const int hh  = blockIdx.y;
    const int d   = threadIdx.x;               // 0..63
    const float p = (float)pos_ids[tok];

    float fr = (float)pow(500000.0, -(double)d / 64.0);
    const float two_pi = 6.283185307179586f;
    float wav = two_pi / fr;
    float f;
    if (wav < 2048.0f)       f = fr;
    else if (wav > 8192.0f)  f = fr * 0.125f;
    else {
        float smooth = (8192.0f / wav - 1.0f) * (1.0f / 3.0f);
        f = (1.0f - smooth) * fr * 0.125f + smooth * fr;
    }
    float ang = p * f;
    float c = cosf(ang), s = sinf(ang);

    if (hh < NH_) {
        const float sc = 0.08838834764831845f;   // 1/sqrt(128) folded into Q
        size_t base = (size_t)tok * (NH_ * HD_) + hh * HD_ + d;
        float x1 = g_q[base], x2 = g_q[base + 64];
        float y1 = (x1 * c - x2 * s) * sc;
        float y2 = (x2 * c + x1 * s) * sc;
        __nv_bfloat16 h1 = __float2bfloat16(y1);
        __nv_bfloat16 h2 = __float2bfloat16(y2);
        g_qh[base]      = h1; g_ql[base]      = __float2bfloat16(y1 - __bfloat162float(h1));
        g_qh[base + 64] = h2; g_ql[base + 64] = __float2bfloat16(y2 - __bfloat162float(h2));
    } else {
        int hk = hh - NH_;
        size_t base = (size_t)tok * (NKV_ * HD_) + hk * HD_ + d;
        float x1 = g_k[base], x2 = g_k[base + 64];
        float y1 = x1 * c - x2 * s;
        float y2 = x2 * c + x1 * s;
        __nv_bfloat16 h1 = __float2bfloat16(y1);
        __nv_bfloat16 h2 = __float2bfloat16(y2);
        g_kh[base]      = h1; g_kl[base]      = __float2bfloat16(y1 - __bfloat162float(h1));
        g_kh[base + 64] = h2; g_kl[base + 64] = __float2bfloat16(y2 - __bfloat162float(h2));
    }
}

// ---------------------------------------------------------------------------
// V transpose + split: g_v [tok][hk][d] fp32 -> g_vth/g_vtl [b][hk][d][s] bf16.
// ---------------------------------------------------------------------------
__global__ void v_split_t() {
    __shared__ float t[32][33];
    const int bhk = blockIdx.x, st = blockIdx.y, dt = blockIdx.z;
    const int b = bhk >> 3, hk = bhk & 7;
    const int tx = threadIdx.x, ty = threadIdx.y;
#pragma unroll
    for (int i = 0; i < 4; ++i) {
        int s = ty + 8 * i;
        t[s][tx] = g_v[(size_t)(b * S_ + st * 32 + s) * (NKV_ * HD_)
                       + hk * HD_ + dt * 32 + tx];
    }
    __syncthreads();
#pragma unroll
    for (int i = 0; i < 4; ++i) {
        int d = ty + 8 * i;
        float v = t[tx][d];
        __nv_bfloat16 h = __float2bfloat16(v);
        size_t idx = (size_t)(bhk * HD_ + dt * 32 + d) * S_ + st * 32 + tx;
        g_vth[idx] = h;
        g_vtl[idx] = __float2bfloat16(v - __bfloat162float(h));
    }
}

// ---------------------------------------------------------------------------
// Tensor-core flash attention (causal, GQA 4:1), 3-term bf16 splits on both
// QK^T and PV. Block = (qtile 128 rows, head, batch); 8 warps x 16 q-rows.
// PV loops interchanged (kf outer, j inner): 16 independent accumulator
// pairs between touches of the same register. ldmatrix offsets precomputed.
// ---------------------------------------------------------------------------
#define FA_SMEM (65536 + 2 * 65536)

__global__ __launch_bounds__(256, 1)
void fa_mma() {
    extern __shared__ char smf[];
    const uint32_t sb = s2u(smf);
    const int qt   = blockIdx.x;               // 0..7 (q-tile of 128)
    const int head = blockIdx.y;
    const int b    = blockIdx.z;
    const int hk   = head >> 2;
    const int bhk  = b * NKV_ + hk;
    const int tid  = threadIdx.x;
    const int wid  = tid >> 5, lane = tid & 31;
    const int tok0 = b * S_ + qt * 128;
    const int nt   = 2 * (qt + 1);             // key tiles of 64

#define FA_LOAD_KV(jt_, st_) do {                                          \
        uint32_t kb_ = sb + 65536 + (st_) * 65536;                         \
        int tokb_ = b * S_ + (jt_) * 64;                                   \
        _Pragma("unroll")                                                  \
        for (int i_ = 0; i_ < 4; ++i_) {                                   \
            int cid_ = tid + 256 * i_;                                     \
            int kr_ = cid_ >> 4, c16_ = cid_ & 15;                         \
            uint32_t so_ = (uint32_t)((c16_ >> 2) * 4096 + kr_ * 64 +      \
                            ((((c16_ & 3) ^ ((kr_ >> 1) & 3))) << 4));     \
            size_t gi_ = (size_t)(tokb_ + kr_) * (NKV_ * HD_)              \
                         + hk * HD_ + c16_ * 8;                            \
            cp16(kb_ + so_,         &g_kh[gi_]);                           \
            cp16(kb_ + 16384 + so_, &g_kl[gi_]);                           \
        }                                                                  \
        _Pragma("unroll")                                                  \
        for (int i_ = 0; i_ < 4; ++i_) {                                   \
            int cid_ = tid + 256 * i_;                                     \
            int dr_ = cid_ >> 3, kc_ = cid_ & 7;                           \
            uint32_t so_ = (uint32_t)((kc_ >> 2) * 8192 + dr_ * 64 +       \
                            ((((kc_ & 3) ^ ((dr_ >> 1) & 3))) << 4));      \
            size_t gi_ = (size_t)(bhk * HD_ + dr_) * S_ + (jt_) * 64       \
                         + kc_ * 8;                                        \
            cp16(kb_ + 32768 + so_, &g_vth[gi_]);                          \
            cp16(kb_ + 49152 + so_, &g_vtl[gi_]);                          \
        }                                                                  \
    } while (0)

    // Q tile (once): [128 rows][128 d] both planes
#pragma unroll
    for (int i = 0; i < 8; ++i) {
        int cid = tid + 256 * i;
        int qr = cid >> 4, c16 = cid & 15;
        uint32_t so = (uint32_t)((c16 >> 2) * 8192 + qr * 64 +
                      ((((c16 & 3) ^ ((qr >> 1) & 3))) << 4));
        size_t gi = (size_t)(tok0 + qr) * (NH_ * HD_) + head * HD_ + c16 * 8;
        cp16(sb + so,         &g_qh[gi]);
        cp16(sb + 32768 + so, &g_ql[gi]);
    }
    FA_LOAD_KV(0, 0);
    CP_COMMIT();

    // ---- precomputed per-lane ldmatrix offsets ----
    uint32_t qoff[2];                     // Q: parity of k-chunk pair
    {
        int row = (wid << 4) + (lane & 15);
        int sw  = (row >> 1) & 3;
#pragma unroll
        for (int par = 0; par < 2; ++par) {
            int cg = 2 * par + (lane >> 4);
            qoff[par] = (uint32_t)(row * 64 + ((cg ^ sw) << 4));
        }
    }
    uint32_t koff[4][2];                  // K: 4 key 16-groups x parity
#pragma unroll
    for (int j = 0; j < 4; ++j) {
        int row = j * 16 + ((lane >> 4) << 3) + (lane & 7);
        int sw  = (row >> 1) & 3;
#pragma unroll
        for (int par = 0; par < 2; ++par) {
            int cg = 2 * par + ((lane >> 3) & 1);
            koff[j][par] = (uint32_t)(row * 64 + ((cg ^ sw) << 4));
        }
    }
    uint32_t voff[8][2];                  // V: 8 d 16-groups x kf parity
#pragma unroll
    for (int j = 0; j < 8; ++j) {
        int row = j * 16 + ((lane >> 4) << 3) + (lane & 7);
        int sw  = (row >> 1) & 3;
#pragma unroll
        for (int par = 0; par < 2; ++par) {
            int cg = 2 * par + ((lane >> 3) & 1);
            voff[j][par] = (uint32_t)(row * 64 + ((cg ^ sw) << 4));
        }
    }

    float o[16][4];
#pragma unroll
    for (int n = 0; n < 16; ++n)
#pragma unroll
        for (int e = 0; e < 4; ++e) o[n][e] = 0.0f;
    float m0 = -1e30f, m1 = -1e30f, l0 = 0.0f, l1 = 0.0f;

    const int r0a = qt * 128 + wid * 16 + (lane >> 2);   // abs q row (thread)

    for (int jt = 0; jt < nt; ++jt) {
        CP_WAIT(0);
        __syncthreads();
        if (jt + 1 < nt) { FA_LOAD_KV(jt + 1, (jt + 1) & 1); CP_COMMIT(); }

        const uint32_t kb  = sb + 65536 + (jt & 1) * 65536;
        const uint32_t KHb = kb, KLb = kb + 16384;
        const uint32_t VHb = kb + 32768, VLb = kb + 49152;

        // ---- S = Q K^T (3-term), warp tile [16 x 64] ----
        float sc[8][4];
#pragma unroll
        for (int f = 0; f < 8; ++f)
#pragma unroll
            for (int e = 0; e < 4; ++e) sc[f][e] = 0.0f;

#pragma unroll
        for (int h8 = 0; h8 < 8; ++h8) {
            const int par = h8 & 1;
            const uint32_t qch = (uint32_t)((h8 >> 1) * 8192);
            const uint32_t kch = (uint32_t)((h8 >> 1) * 4096);
            uint32_t qh_f[4], ql_f[4];
            ldm_x4(qh_f, sb + qch + qoff[par]);
            ldm_x4(ql_f, sb + 32768 + qch + qoff[par]);
            uint32_t kh_f[4][4], kl_f[4][4];
#pragma unroll
            for (int j = 0; j < 4; ++j) {
                ldm_x4(kh_f[j], KHb + kch + koff[j][par]);
                ldm_x4(kl_f[j], KLb + kch + koff[j][par]);
            }
#pragma unroll
            for (int j = 0; j < 4; ++j) {
                mma16816(sc[2 * j],     qh_f, &kh_f[j][0]);
                mma16816(sc[2 * j + 1], qh_f, &kh_f[j][2]);
                mma16816(sc[2 * j],     qh_f, &kl_f[j][0]);
                mma16816(sc[2 * j + 1], qh_f, &kl_f[j][2]);
                mma16816(sc[2 * j],     ql_f, &kh_f[j][0]);
                mma16816(sc[2 * j + 1], ql_f, &kh_f[j][2]);
            }
        }

        // ---- causal mask (diagonal tiles only) ----
        if (jt >= 2 * qt) {
            int kk0 = jt * 64 + 2 * (lane & 3);
#pragma unroll
            for (int f = 0; f < 8; ++f) {
                int k0 = kk0 + 8 * f;
                if (k0     > r0a)     sc[f][0] = -1e30f;
                if (k0 + 1 > r0a)     sc[f][1] = -1e30f;
                if (k0     > r0a + 8) sc[f][2] = -1e30f;
                if (k0 + 1 > r0a + 8) sc[f][3] = -1e30f;
            }
        }

        // ---- online softmax (rows r0a, r0a+8; 4-lane groups per row) ----
        float t0 = -1e30f, t1 = -1e30f;
#pragma unroll
        for (int f = 0; f < 8; ++f) {
            t0 = fmaxf(t0, fmaxf(sc[f][0], sc[f][1]));
            t1 = fmaxf(t1, fmaxf(sc[f][2], sc[f][3]));
        }
        t0 = fmaxf(t0, __shfl_xor_sync(0xffffffffu, t0, 1));
        t0 = fmaxf(t0, __shfl_xor_sync(0xffffffffu, t0, 2));
        t1 = fmaxf(t1, __shfl_xor_sync(0xffffffffu, t1, 1));
        t1 = fmaxf(t1, __shfl_xor_sync(0xffffffffu, t1, 2));
        float m0n = fmaxf(m0, t0), m1n = fmaxf(m1, t1);
        float c0 = __expf(m0 - m0n), c1 = __expf(m1 - m1n);
        m0 = m0n; m1 = m1n;

        float rs0 = 0.0f, rs1 = 0.0f;
#pragma unroll
        for (int f = 0; f < 8; ++f) {
            sc[f][0] = __expf(sc[f][0] - m0); rs0 += sc[f][0];
            sc[f][1] = __expf(sc[f][1] - m0); rs0 += sc[f][1];
            sc[f][2] = __expf(sc[f][2] - m1); rs1 += sc[f][2];
            sc[f][3] = __expf(sc[f][3] - m1); rs1 += sc[f][3];
        }
        rs0 += __shfl_xor_sync(0xffffffffu, rs0, 1);
        rs0 += __shfl_xor_sync(0xffffffffu, rs0, 2);
        rs1 += __shfl_xor_sync(0xffffffffu, rs1, 1);
        rs1 += __shfl_xor_sync(0xffffffffu, rs1, 2);
        l0 = l0 * c0 + rs0;
        l1 = l1 * c1 + rs1;
#pragma unroll
        for (int n = 0; n < 16; ++n) {
            o[n][0] *= c0; o[n][1] *= c0;
            o[n][2] *= c1; o[n][3] *= c1;
        }

        // ---- pack P into A-fragments (hi + residual lo), in registers ----
        uint32_t pah[4][4], pal[4][4];
#pragma unroll
        for (int kf = 0; kf < 4; ++kf) {
            const int f0 = 2 * kf, f1 = 2 * kf + 1;
            pah[kf][0] = packbf2(sc[f0][0], sc[f0][1]);
            pah[kf][1] = packbf2(sc[f0][2], sc[f0][3]);
            pah[kf][2] = packbf2(sc[f1][0], sc[f1][1]);
            pah[kf][3] = packbf2(sc[f1][2], sc[f1][3]);
            __nv_bfloat162 h0 = *reinterpret_cast<__nv_bfloat162*>(&pah[kf][0]);
            __nv_bfloat162 h1 = *reinterpret_cast<__nv_bfloat162*>(&pah[kf][1]);
            __nv_bfloat162 h2 = *reinterpret_cast<__nv_bfloat162*>(&pah[kf][2]);
            __nv_bfloat162 h3 = *reinterpret_cast<__nv_bfloat162*>(&pah[kf][3]);
            pal[kf][0] = packbf2(sc[f0][0] - __bfloat162float(h0.x),
                                 sc[f0][1] - __bfloat162float(h0.y));
            pal[kf][1] = packbf2(sc[f0][2] - __bfloat162float(h1.x),
                                 sc[f0][3] - __bfloat162float(h1.y));
            pal[kf][2] = packbf2(sc[f1][0] - __bfloat162float(h2.x),
                                 sc[f1][1] - __bfloat162float(h2.y));
            pal[kf][3] = packbf2(sc[f1][2] - __bfloat162float(h3.x),
                                 sc[f1][3] - __bfloat162float(h3.y));
        }

        // ---- O += P V (3-term). kf OUTER, j INNER: 16 independent
        //      accumulator pairs between touches of the same register. ----
#pragma unroll
        for (int kf = 0; kf < 4; ++kf) {
            const int par = kf & 1;
            const uint32_t vch = (uint32_t)((kf >> 1) * 8192);
#pragma unroll
            for (int j = 0; j < 8; ++j) {
                uint32_t vh_f[4], vl_f[4];
                ldm_x4(vh_f, VHb + vch + voff[j][par]);
                ldm_x4(vl_f, VLb + vch + voff[j][par]);
                mma16816(o[2 * j],     pah[kf], &vh_f[0]);
                mma16816(o[2 * j + 1], pah[kf], &vh_f[2]);
                mma16816(o[2 * j],     pal[kf], &vh_f[0]);
                mma16816(o[2 * j + 1], pal[kf], &vh_f[2]);
                mma16816(o[2 * j],     pah[kf], &vl_f[0]);
                mma16816(o[2 * j + 1], pah[kf], &vl_f[2]);
            }
        }
    }

    // ---- epilogue: normalize, split, write attn hi/lo planes ----
    const float inv0 = 1.0f / l0, inv1 = 1.0f / l1;
    const size_t tr0 = (size_t)(b * S_ + qt * 128 + wid * 16 + (lane >> 2));
#pragma unroll
    for (int n = 0; n < 16; ++n) {
        int d = n * 8 + 2 * (lane & 3);
        {
            float v0 = o[n][0] * inv0, v1 = o[n][1] * inv0;
            uint32_t hp = packbf2(v0, v1);
            __nv_bfloat162 hh = *reinterpret_cast<__nv_bfloat162*>(&hp);
            uint32_t lp = packbf2(v0 - __bfloat162float(hh.x),
                                  v1 - __bfloat162float(hh.y));
            size_t idx = tr0 * (NH_ * HD_) + head * HD_ + d;
            *(uint32_t*)&g_at_h[idx] = hp;
            *(uint32_t*)&g_at_l[idx] = lp;
        }
        {
            float v0 = o[n][2] * inv1, v1 = o[n][3] * inv1;
            uint32_t hp = packbf2(v0, v1);
            __nv_bfloat162 hh = *reinterpret_cast<__nv_bfloat162*>(&hp);
            uint32_t lp = packbf2(v0 - __bfloat162float(hh.x),
                                  v1 - __bfloat162float(hh.y));
            size_t idx = (tr0 + 8) * (NH_ * HD_) + head * HD_ + d;
            *(uint32_t*)&g_at_h[idx] = hp;
            *(uint32_t*)&g_at_l[idx] = lp;
        }
    }
#undef FA_LOAD_KV
}

// ---------------------------------------------------------------------------
// Launch: split -> mma GEMMs (QKV) -> rope_split -> v transpose-split ->
// tensor-core FA -> mma GEMM (O). kv_cache append skipped (identity).
// ---------------------------------------------------------------------------
extern "C" void kernel_launch(void* const* d_in, const int* in_sizes, int n_in,
                              void* d_out, int out_size) {
    const float* hs = (const float*)d_in[0];
    const float* wq = (const float*)d_in[1];
    const float* wk = (const float*)d_in[2];
    const float* wv = (const float*)d_in[3];
    const float* wo = (const float*)d_in[4];
    const int* pos  = (const int*)d_in[6];
    float* out = (float*)d_out;

    float *pq, *pk, *pv;
    cudaGetSymbolAddress((void**)&pq, g_q);
    cudaGetSymbolAddress((void**)&pk, g_k);
    cudaGetSymbolAddress((void**)&pv, g_v);

    __nv_bfloat16 *hsh, *hsl, *wqh, *wql, *wkh, *wkl, *wvh, *wvl, *woh, *wol, *ath, *atl;
    cudaGetSymbolAddress((void**)&hsh, g_hs_h); cudaGetSymbolAddress((void**)&hsl, g_hs_l);
    cudaGetSymbolAddress((void**)&wqh, g_wq_h); cudaGetSymbolAddress((void**)&wql, g_wq_l);
    cudaGetSymbolAddress((void**)&wkh, g_wk_h); cudaGetSymbolAddress((void**)&wkl, g_wk_l);
    cudaGetSymbolAddress((void**)&wvh, g_wv_h); cudaGetSymbolAddress((void**)&wvl, g_wv_l);
    cudaGetSymbolAddress((void**)&woh, g_wo_h); cudaGetSymbolAddress((void**)&wol, g_wo_l);
    cudaGetSymbolAddress((void**)&ath, g_at_h); cudaGetSymbolAddress((void**)&atl, g_at_l);

    cudaFuncSetAttribute(gemm_mma_split, cudaFuncAttributeMaxDynamicSharedMemorySize,
                         G_SMEM);
    cudaFuncSetAttribute(fa_mma, cudaFuncAttributeMaxDynamicSharedMemorySize,
                         FA_SMEM);

    const int BIG4 = (NNZ_ * HID_) / 1024;
    const int SML4 = (NKV_ * HD_ * HID_) / 1024;

    // split inputs/weights to bf16 hi/lo planes
    split_fp32_bf16<<<BIG4, 256>>>(hs, hsh, hsl);
    split_fp32_bf16<<<BIG4, 256>>>(wq, wqh, wql);
    split_fp32_bf16<<<SML4, 256>>>(wk, wkh, wkl);
    split_fp32_bf16<<<SML4, 256>>>(wv, wvh, wvl);
    split_fp32_bf16<<<BIG4, 256>>>(wo, woh, wol);

    // QKV projections (tensor cores via mma.sync)
    gemm_mma_split<<<dim3((NH_ * HD_) / 256, NNZ_ / 128), 256, G_SMEM>>>(
        hsh, hsl, wqh, wql, pq, NH_ * HD_, HID_);
    gemm_mma_split<<<dim3((NKV_ * HD_) / 256, NNZ_ / 128), 256, G_SMEM>>>(
        hsh, hsl, wkh, wkl, pk, NKV_ * HD_, HID_);
    gemm_mma_split<<<dim3((NKV_ * HD_) / 256, NNZ_ / 128), 256, G_SMEM>>>(
        hsh, hsl, wvh, wvl, pv, NKV_ * HD_, HID_);

    // RoPE + split (Q scaled), V transpose + split
    rope_split<<<dim3(NNZ_, NH_ + NKV_), 64>>>(pos);
    v_split_t<<<dim3(B_ * NKV_, S_ / 32, HD_ / 32), dim3(32, 8)>>>();

    // Tensor-core causal GQA flash attention -> attn hi/lo planes
    fa_mma<<<dim3(S_ / 128, NH_, B_), 256, FA_SMEM>>>();

    // O projection
    gemm_mma_split<<<dim3(HID_ / 256, NNZ_ / 128), 256, G_SMEM>>>(
        ath, atl, woh, wol, out, HID_, NH_ * HD_);
}

// round 13
// speedup vs baseline: 1.5843x; 1.0026x over previous
#include <cuda_runtime.h>
#include <cuda_bf16.h>
#include <math.h>
#include <stdint.h>

// Problem constants
#define B_    4
#define S_    1024
#define HID_  4096
#define NH_   32
#define NKV_  8
#define HD_   128
#define NNZ_  (B_ * S_)

// ---------------------------------------------------------------------------
// Scratch (static device allocations; runtime alloc is forbidden)
// ---------------------------------------------------------------------------
__device__ float g_q[(size_t)NNZ_ * NH_ * HD_];     // fp32 proj outputs
__device__ float g_k[(size_t)NNZ_ * NKV_ * HD_];
__device__ float g_v[(size_t)NNZ_ * NKV_ * HD_];

// bf16 split planes (hi/lo)
__device__ __nv_bfloat16 g_hs_h[(size_t)NNZ_ * HID_];
__device__ __nv_bfloat16 g_hs_l[(size_t)NNZ_ * HID_];
__device__ __nv_bfloat16 g_wq_h[(size_t)(NH_ * HD_) * HID_];
__device__ __nv_bfloat16 g_wq_l[(size_t)(NH_ * HD_) * HID_];
__device__ __nv_bfloat16 g_wk_h[(size_t)(NKV_ * HD_) * HID_];
__device__ __nv_bfloat16 g_wk_l[(size_t)(NKV_ * HD_) * HID_];
__device__ __nv_bfloat16 g_wv_h[(size_t)(NKV_ * HD_) * HID_];
__device__ __nv_bfloat16 g_wv_l[(size_t)(NKV_ * HD_) * HID_];
__device__ __nv_bfloat16 g_wo_h[(size_t)HID_ * (NH_ * HD_)];
__device__ __nv_bfloat16 g_wo_l[(size_t)HID_ * (NH_ * HD_)];
__device__ __nv_bfloat16 g_at_h[(size_t)NNZ_ * (NH_ * HD_)];   // FA output planes
__device__ __nv_bfloat16 g_at_l[(size_t)NNZ_ * (NH_ * HD_)];

// roped/scaled Q,K and transposed V planes for tensor-core FA
__device__ __nv_bfloat16 g_qh[(size_t)NNZ_ * NH_ * HD_];
__device__ __nv_bfloat16 g_ql[(size_t)NNZ_ * NH_ * HD_];
__device__ __nv_bfloat16 g_kh[(size_t)NNZ_ * NKV_ * HD_];
__device__ __nv_bfloat16 g_kl[(size_t)NNZ_ * NKV_ * HD_];
__device__ __nv_bfloat16 g_vth[(size_t)B_ * NKV_ * HD_ * S_];  // [b][hk][d][s]
__device__ __nv_bfloat16 g_vtl[(size_t)B_ * NKV_ * HD_ * S_];

// ---------------------------------------------------------------------------
// PTX helpers — sm_80-compatible vocabulary ONLY (harness PTX targets
// compute_103 without the 'a' suffix, so tcgen05/TMA are unavailable).
// ---------------------------------------------------------------------------
__device__ __forceinline__ uint32_t s2u(const void* p) {
    uint32_t a;
    asm("{ .reg .u64 t; cvta.to.shared.u64 t, %1; cvt.u32.u64 %0, t; }"
        : "=r"(a) : "l"(p));
    return a;
}

__device__ __forceinline__ void cp16(uint32_t s, const void* g) {
    asm volatile("cp.async.cg.shared.global [%0], [%1], 16;" :: "r"(s), "l"(g));
}
#define CP_COMMIT() asm volatile("cp.async.commit_group;" ::: "memory")
#define CP_WAIT(n)  asm volatile("cp.async.wait_group %0;" :: "n"(n) : "memory")

__device__ __forceinline__ void ldm_x4(uint32_t* r, uint32_t addr) {
    asm volatile("ldmatrix.sync.aligned.m8n8.x4.shared.b16 {%0,%1,%2,%3}, [%4];"
                 : "=r"(r[0]), "=r"(r[1]), "=r"(r[2]), "=r"(r[3]) : "r"(addr));
}

__device__ __forceinline__ void mma16816(float* d, const uint32_t* a,
                                         const uint32_t* b) {
    asm volatile(
        "mma.sync.aligned.m16n8k16.row.col.f32.bf16.bf16.f32 "
        "{%0,%1,%2,%3}, {%4,%5,%6,%7}, {%8,%9}, {%0,%1,%2,%3};"
        : "+f"(d[0]), "+f"(d[1]), "+f"(d[2]), "+f"(d[3])
        : "r"(a[0]), "r"(a[1]), "r"(a[2]), "r"(a[3]), "r"(b[0]), "r"(b[1]));
}

__device__ __forceinline__ uint32_t packbf2(float lo, float hi) {
    __nv_bfloat162 t = __floats2bfloat162_rn(lo, hi);   // .x=lo (low 16 bits)
    return *reinterpret_cast<uint32_t*>(&t);
}

// ---------------------------------------------------------------------------
// Split fp32 -> (bf16 hi, bf16 lo) planes.
// ---------------------------------------------------------------------------
__global__ void split_fp32_bf16(const float* __restrict__ src,
                                __nv_bfloat16* __restrict__ hi,
                                __nv_bfloat16* __restrict__ lo) {
    size_t i = (size_t)blockIdx.x * blockDim.x + threadIdx.x;
    float4 v = ((const float4*)src)[i];
    float x[4] = {v.x, v.y, v.z, v.w};
    union { __nv_bfloat16 b[4]; ushort4 u; } H, L;
#pragma unroll
    for (int j = 0; j < 4; ++j) {
        H.b[j] = __float2bfloat16(x[j]);
        L.b[j] = __float2bfloat16(x[j] - __bfloat162float(H.b[j]));
    }
    ((ushort4*)hi)[i] = H.u;
    ((ushort4*)lo)[i] = L.u;
}

// ---------------------------------------------------------------------------
// bf16-split GEMM via mma.sync (unchanged — pinned at legacy HMMA pipe rate).
// ---------------------------------------------------------------------------
#define A_PLANE   8192
#define B_PLANE   16384
#define STAGE_B   (2 * A_PLANE + 2 * B_PLANE)
#define G_SMEM    (3 * STAGE_B)

__global__ __launch_bounds__(256, 1)
void gemm_mma_split(const __nv_bfloat16* __restrict__ Ah,
                    const __nv_bfloat16* __restrict__ Al,
                    const __nv_bfloat16* __restrict__ Bh,
                    const __nv_bfloat16* __restrict__ Bl,
                    float* __restrict__ C, int N, int K) {
    extern __shared__ char smc[];
    const uint32_t sb = s2u(smc);
    const int tid  = threadIdx.x;
    const int wid  = tid >> 5, lane = tid & 31;
    const int wm   = wid >> 2, wn = wid & 3;
    const int m0   = blockIdx.y * 128, n0 = blockIdx.x * 256;

    const int lrow = tid >> 1;
    const int cg0  = (tid & 1) * 2;
    const __nv_bfloat16* gAh = Ah + (size_t)(m0 + lrow) * K + cg0 * 8;
    const __nv_bfloat16* gAl = Al + (size_t)(m0 + lrow) * K + cg0 * 8;
    const __nv_bfloat16* gBh = Bh + (size_t)(n0 + lrow) * K + cg0 * 8;
    const __nv_bfloat16* gBl = Bl + (size_t)(n0 + lrow) * K + cg0 * 8;
    const size_t rowskip = (size_t)128 * K;
    const int swl = (lrow >> 1) & 3;
    uint32_t soff[2];
    soff[0] = lrow * 64 + (((cg0 + 0) ^ swl) << 4);
    soff[1] = lrow * 64 + (((cg0 + 1) ^ swl) << 4);

#define LOAD_CHUNK(kt, st) do {                                           \
        uint32_t b_ = sb + (st) * STAGE_B;                                \
        size_t  g_ = (size_t)(kt) * 32;                                   \
        cp16(b_ + soff[0],                      gAh + g_);                \
        cp16(b_ + soff[1],                      gAh + g_ + 8);            \
        cp16(b_ + A_PLANE + soff[0],            gAl + g_);                \
        cp16(b_ + A_PLANE + soff[1],            gAl + g_ + 8);            \
        cp16(b_ + 2 * A_PLANE + soff[0],        gBh + g_);                \
        cp16(b_ + 2 * A_PLANE + soff[1],        gBh + g_ + 8);            \
        cp16(b_ + 2 * A_PLANE + 8192 + soff[0], gBh + g_ + rowskip);      \
        cp16(b_ + 2 * A_PLANE + 8192 + soff[1], gBh + g_ + rowskip + 8);  \
        cp16(b_ + 2 * A_PLANE + B_PLANE + soff[0],        gBl + g_);      \
        cp16(b_ + 2 * A_PLANE + B_PLANE + soff[1],        gBl + g_ + 8);  \
        cp16(b_ + 2 * A_PLANE + B_PLANE + 8192 + soff[0], gBl + g_ + rowskip);     \
        cp16(b_ + 2 * A_PLANE + B_PLANE + 8192 + soff[1], gBl + g_ + rowskip + 8); \
        CP_COMMIT();                                                      \
    } while (0)

    uint32_t aoff[4][2];
#pragma unroll
    for (int t = 0; t < 4; ++t) {
        int row = wm * 64 + t * 16 + (lane & 15);
        int sw  = (row >> 1) & 3;
#pragma unroll
        for (int h = 0; h < 2; ++h) {
            int cg = 2 * h + (lane >> 4);
            aoff[t][h] = row * 64 + ((cg ^ sw) << 4);
        }
    }
    uint32_t boff[4][2];
#pragma unroll
    for (int j = 0; j < 4; ++j) {
        int row = wn * 64 + j * 16 + ((lane >> 4) << 3) + (lane & 7);
        int sw  = (row >> 1) & 3;
#pragma unroll
        for (int h = 0; h < 2; ++h) {
            int cg = 2 * h + ((lane >> 3) & 1);
            boff[j][h] = row * 64 + ((cg ^ sw) << 4);
        }
    }

    float acc[4][8][4];
#pragma unroll
    for (int t = 0; t < 4; ++t)
#pragma unroll
        for (int n = 0; n < 8; ++n)
#pragma unroll
            for (int e = 0; e < 4; ++e) acc[t][n][e] = 0.0f;

    const int nkt = K >> 5;
    LOAD_CHUNK(0, 0);
    LOAD_CHUNK(1, 1);

    for (int kt = 0; kt < nkt; ++kt) {
        const int s = kt % 3;
        if (kt + 1 < nkt) { CP_WAIT(1); } else { CP_WAIT(0); }
        __syncthreads();
        if (kt + 2 < nkt) LOAD_CHUNK(kt + 2, (kt + 2) % 3);

        const uint32_t pA_h = sb + s * STAGE_B;
        const uint32_t pA_l = pA_h + A_PLANE;
        const uint32_t pB_h = pA_h + 2 * A_PLANE;
        const uint32_t pB_l = pB_h + B_PLANE;

#pragma unroll
        for (int h = 0; h < 2; ++h) {
            uint32_t ah[4][4], al[4][4], bh[4][4], bl[4][4];
#pragma unroll
            for (int t = 0; t < 4; ++t) {
                ldm_x4(ah[t], pA_h + aoff[t][h]);
                ldm_x4(al[t], pA_l + aoff[t][h]);
            }
#pragma unroll
            for (int j = 0; j < 4; ++j) {
                ldm_x4(bh[j], pB_h + boff[j][h]);
                ldm_x4(bl[j], pB_l + boff[j][h]);
            }
#pragma unroll
            for (int t = 0; t < 4; ++t)
#pragma unroll
                for (int j = 0; j < 4; ++j) {
                    mma16816(acc[t][2 * j],     ah[t], &bh[j][0]);
                    mma16816(acc[t][2 * j + 1], ah[t], &bh[j][2]);
                    mma16816(acc[t][2 * j],     ah[t], &bl[j][0]);
                    mma16816(acc[t][2 * j + 1], ah[t], &bl[j][2]);
                    mma16816(acc[t][2 * j],     al[t], &bh[j][0]);
                    mma16816(acc[t][2 * j + 1], al[t], &bh[j][2]);
                }
        }
    }

    float* Cw = C + (size_t)(m0 + wm * 64) * N + n0 + wn * 64;
#pragma unroll
    for (int t = 0; t < 4; ++t)
#pragma unroll
        for (int n = 0; n < 8; ++n) {
            int r = t * 16 + (lane >> 2);
            int c = n * 8 + (lane & 3) * 2;
            *(float2*)&Cw[(size_t)r * N + c] =
                make_float2(acc[t][n][0], acc[t][n][1]);
            *(float2*)&Cw[(size_t)(r + 8) * N + c] =
                make_float2(acc[t][n][2], acc[t][n][3]);
        }
#undef LOAD_CHUNK
}

// ---------------------------------------------------------------------------
// RoPE + bf16 split. grid (NNZ, 40): y<32 -> Q head (scaled), else K head.
// ---------------------------------------------------------------------------
__global__ void rope_split(const int* __restrict__ pos_ids) {
    const int tok = blockIdx.x;
    const int hh  = blockIdx.y;
    const int d   = threadIdx.x;               // 0..63
    const float p = (float)pos_ids[tok];

    float fr = (float)pow(500000.0, -(double)d / 64.0);
    const float two_pi = 6.283185307179586f;
    float wav = two_pi / fr;
    float f;
    if (wav < 2048.0f)       f = fr;
    else if (wav > 8192.0f)  f = fr * 0.125f;
    else {
        float smooth = (8192.0f / wav - 1.0f) * (1.0f / 3.0f);
        f = (1.0f - smooth) * fr * 0.125f + smooth * fr;
    }
    float ang = p * f;
    float c = cosf(ang), s = sinf(ang);

    if (hh < NH_) {
        const float sc = 0.08838834764831845f;   // 1/sqrt(128) folded into Q
        size_t base = (size_t)tok * (NH_ * HD_) + hh * HD_ + d;
        float x1 = g_q[base], x2 = g_q[base + 64];
        float y1 = (x1 * c - x2 * s) * sc;
        float y2 = (x2 * c + x1 * s) * sc;
        __nv_bfloat16 h1 = __float2bfloat16(y1);
        __nv_bfloat16 h2 = __float2bfloat16(y2);
        g_qh[base]      = h1; g_ql[base]      = __float2bfloat16(y1 - __bfloat162float(h1));
        g_qh[base + 64] = h2; g_ql[base + 64] = __float2bfloat16(y2 - __bfloat162float(h2));
    } else {
        int hk = hh - NH_;
        size_t base = (size_t)tok * (NKV_ * HD_) + hk * HD_ + d;
        float x1 = g_k[base], x2 = g_k[base + 64];
        float y1 = x1 * c - x2 * s;
        float y2 = x2 * c + x1 * s;
        __nv_bfloat16 h1 = __float2bfloat16(y1);
        __nv_bfloat16 h2 = __float2bfloat16(y2);
        g_kh[base]      = h1; g_kl[base]      = __float2bfloat16(y1 - __bfloat162float(h1));
        g_kh[base + 64] = h2; g_kl[base + 64] = __float2bfloat16(y2 - __bfloat162float(h2));
    }
}

// ---------------------------------------------------------------------------
// V transpose + split: g_v [tok][hk][d] fp32 -> g_vth/g_vtl [b][hk][d][s] bf16.
// ---------------------------------------------------------------------------
__global__ void v_split_t() {
    __shared__ float t[32][33];
    const int bhk = blockIdx.x, st = blockIdx.y, dt = blockIdx.z;
    const int b = bhk >> 3, hk = bhk & 7;
    const int tx = threadIdx.x, ty = threadIdx.y;
#pragma unroll
    for (int i = 0; i < 4; ++i) {
        int s = ty + 8 * i;
        t[s][tx] = g_v[(size_t)(b * S_ + st * 32 + s) * (NKV_ * HD_)
                       + hk * HD_ + dt * 32 + tx];
    }
    __syncthreads();
#pragma unroll
    for (int i = 0; i < 4; ++i) {
        int d = ty + 8 * i;
        float v = t[tx][d];
        __nv_bfloat16 h = __float2bfloat16(v);
        size_t idx = (size_t)(bhk * HD_ + dt * 32 + d) * S_ + st * 32 + tx;
        g_vth[idx] = h;
        g_vtl[idx] = __float2bfloat16(v - __bfloat162float(h));
    }
}

// ---------------------------------------------------------------------------
// Tensor-core flash attention (causal, GQA 4:1), 3-term bf16 splits on both
// QK^T and PV. Block = (qtile 128 rows, head, batch); 8 warps x 16 q-rows.
// R13: QK mma block reordered term-major (all j for hh, then hl, then lh) —
// accumulator reuse spacing 2 -> 8, same fix that rescued PV in R12. The
// per-accumulator accumulation ORDER is unchanged (hh->hl->lh per h8), so
// the result is bit-identical to R12 (rel_err must repeat exactly).
// ---------------------------------------------------------------------------
#define FA_SMEM (65536 + 2 * 65536)

__global__ __launch_bounds__(256, 1)
void fa_mma() {
    extern __shared__ char smf[];
    const uint32_t sb = s2u(smf);
    const int qt   = blockIdx.x;               // 0..7 (q-tile of 128)
    const int head = blockIdx.y;
    const int b    = blockIdx.z;
    const int hk   = head >> 2;
    const int bhk  = b * NKV_ + hk;
    const int tid  = threadIdx.x;
    const int wid  = tid >> 5, lane = tid & 31;
    const int tok0 = b * S_ + qt * 128;
    const int nt   = 2 * (qt + 1);             // key tiles of 64

#define FA_LOAD_KV(jt_, st_) do {                                          \
        uint32_t kb_ = sb + 65536 + (st_) * 65536;                         \
        int tokb_ = b * S_ + (jt_) * 64;                                   \
        _Pragma("unroll")                                                  \
        for (int i_ = 0; i_ < 4; ++i_) {                                   \
            int cid_ = tid + 256 * i_;                                     \
            int kr_ = cid_ >> 4, c16_ = cid_ & 15;                         \
            uint32_t so_ = (uint32_t)((c16_ >> 2) * 4096 + kr_ * 64 +      \
                            ((((c16_ & 3) ^ ((kr_ >> 1) & 3))) << 4));     \
            size_t gi_ = (size_t)(tokb_ + kr_) * (NKV_ * HD_)              \
                         + hk * HD_ + c16_ * 8;                            \
            cp16(kb_ + so_,         &g_kh[gi_]);                           \
            cp16(kb_ + 16384 + so_, &g_kl[gi_]);                           \
        }                                                                  \
        _Pragma("unroll")                                                  \
        for (int i_ = 0; i_ < 4; ++i_) {                                   \
            int cid_ = tid + 256 * i_;                                     \
            int dr_ = cid_ >> 3, kc_ = cid_ & 7;                           \
            uint32_t so_ = (uint32_t)((kc_ >> 2) * 8192 + dr_ * 64 +       \
                            ((((kc_ & 3) ^ ((dr_ >> 1) & 3))) << 4));      \
            size_t gi_ = (size_t)(bhk * HD_ + dr_) * S_ + (jt_) * 64       \
                         + kc_ * 8;                                        \
            cp16(kb_ + 32768 + so_, &g_vth[gi_]);                          \
            cp16(kb_ + 49152 + so_, &g_vtl[gi_]);                          \
        }                                                                  \
    } while (0)

    // Q tile (once): [128 rows][128 d] both planes
#pragma unroll
    for (int i = 0; i < 8; ++i) {
        int cid = tid + 256 * i;
        int qr = cid >> 4, c16 = cid & 15;
        uint32_t so = (uint32_t)((c16 >> 2) * 8192 + qr * 64 +
                      ((((c16 & 3) ^ ((qr >> 1) & 3))) << 4));
        size_t gi = (size_t)(tok0 + qr) * (NH_ * HD_) + head * HD_ + c16 * 8;
        cp16(sb + so,         &g_qh[gi]);
        cp16(sb + 32768 + so, &g_ql[gi]);
    }
    FA_LOAD_KV(0, 0);
    CP_COMMIT();

    // ---- precomputed per-lane ldmatrix offsets ----
    uint32_t qoff[2];                     // Q: parity of k-chunk pair
    {
        int row = (wid << 4) + (lane & 15);
        int sw  = (row >> 1) & 3;
#pragma unroll
        for (int par = 0; par < 2; ++par) {
            int cg = 2 * par + (lane >> 4);
            qoff[par] = (uint32_t)(row * 64 + ((cg ^ sw) << 4));
        }
    }
    uint32_t koff[4][2];                  // K: 4 key 16-groups x parity
#pragma unroll
    for (int j = 0; j < 4; ++j) {
        int row = j * 16 + ((lane >> 4) << 3) + (lane & 7);
        int sw  = (row >> 1) & 3;
#pragma unroll
        for (int par = 0; par < 2; ++par) {
            int cg = 2 * par + ((lane >> 3) & 1);
            koff[j][par] = (uint32_t)(row * 64 + ((cg ^ sw) << 4));
        }
    }
    uint32_t voff[8][2];                  // V: 8 d 16-groups x kf parity
#pragma unroll
    for (int j = 0; j < 8; ++j) {
        int row = j * 16 + ((lane >> 4) << 3) + (lane & 7);
        int sw  = (row >> 1) & 3;
#pragma unroll
        for (int par = 0; par < 2; ++par) {
            int cg = 2 * par + ((lane >> 3) & 1);
            voff[j][par] = (uint32_t)(row * 64 + ((cg ^ sw) << 4));
        }
    }

    float o[16][4];
#pragma unroll
    for (int n = 0; n < 16; ++n)
#pragma unroll
        for (int e = 0; e < 4; ++e) o[n][e] = 0.0f;
    float m0 = -1e30f, m1 = -1e30f, l0 = 0.0f, l1 = 0.0f;

    const int r0a = qt * 128 + wid * 16 + (lane >> 2);   // abs q row (thread)

    for (int jt = 0; jt < nt; ++jt) {
        CP_WAIT(0);
        __syncthreads();
        if (jt + 1 < nt) { FA_LOAD_KV(jt + 1, (jt + 1) & 1); CP_COMMIT(); }

        const uint32_t kb  = sb + 65536 + (jt & 1) * 65536;
        const uint32_t KHb = kb, KLb = kb + 16384;
        const uint32_t VHb = kb + 32768, VLb = kb + 49152;

        // ---- S = Q K^T (3-term), warp tile [16 x 64] ----
        float sc[8][4];
#pragma unroll
        for (int f = 0; f < 8; ++f)
#pragma unroll
            for (int e = 0; e < 4; ++e) sc[f][e] = 0.0f;

#pragma unroll
        for (int h8 = 0; h8 < 8; ++h8) {
            const int par = h8 & 1;
            const uint32_t qch = (uint32_t)((h8 >> 1) * 8192);
            const uint32_t kch = (uint32_t)((h8 >> 1) * 4096);
            uint32_t qh_f[4], ql_f[4];
            ldm_x4(qh_f, sb + qch + qoff[par]);
            ldm_x4(ql_f, sb + 32768 + qch + qoff[par]);
            uint32_t kh_f[4][4], kl_f[4][4];
#pragma unroll
            for (int j = 0; j < 4; ++j) {
                ldm_x4(kh_f[j], KHb + kch + koff[j][par]);
                ldm_x4(kl_f[j], KLb + kch + koff[j][par]);
            }
            // term-major: accumulator reuse spacing = 8 (was 2)
#pragma unroll
            for (int j = 0; j < 4; ++j) {
                mma16816(sc[2 * j],     qh_f, &kh_f[j][0]);
                mma16816(sc[2 * j + 1], qh_f, &kh_f[j][2]);
            }
#pragma unroll
            for (int j = 0; j < 4; ++j) {
                mma16816(sc[2 * j],     qh_f, &kl_f[j][0]);
                mma16816(sc[2 * j + 1], qh_f, &kl_f[j][2]);
            }
#pragma unroll
            for (int j = 0; j < 4; ++j) {
                mma16816(sc[2 * j],     ql_f, &kh_f[j][0]);
                mma16816(sc[2 * j + 1], ql_f, &kh_f[j][2]);
            }
        }

        // ---- causal mask (diagonal tiles only) ----
        if (jt >= 2 * qt) {
            int kk0 = jt * 64 + 2 * (lane & 3);
#pragma unroll
            for (int f = 0; f < 8; ++f) {
                int k0 = kk0 + 8 * f;
                if (k0     > r0a)     sc[f][0] = -1e30f;
                if (k0 + 1 > r0a)     sc[f][1] = -1e30f;
                if (k0     > r0a + 8) sc[f][2] = -1e30f;
                if (k0 + 1 > r0a + 8) sc[f][3] = -1e30f;
            }
        }

        // ---- online softmax (rows r0a, r0a+8; 4-lane groups per row) ----
        float t0 = -1e30f, t1 = -1e30f;
#pragma unroll
        for (int f = 0; f < 8; ++f) {
            t0 = fmaxf(t0, fmaxf(sc[f][0], sc[f][1]));
            t1 = fmaxf(t1, fmaxf(sc[f][2], sc[f][3]));
        }
        t0 = fmaxf(t0, __shfl_xor_sync(0xffffffffu, t0, 1));
        t0 = fmaxf(t0, __shfl_xor_sync(0xffffffffu, t0, 2));
        t1 = fmaxf(t1, __shfl_xor_sync(0xffffffffu, t1, 1));
        t1 = fmaxf(t1, __shfl_xor_sync(0xffffffffu, t1, 2));
        float m0n = fmaxf(m0, t0), m1n = fmaxf(m1, t1);
        float c0 = __expf(m0 - m0n), c1 = __expf(m1 - m1n);
        m0 = m0n; m1 = m1n;

        float rs0 = 0.0f, rs1 = 0.0f;
#pragma unroll
        for (int f = 0; f < 8; ++f) {
            sc[f][0] = __expf(sc[f][0] - m0); rs0 += sc[f][0];
            sc[f][1] = __expf(sc[f][1] - m0); rs0 += sc[f][1];
            sc[f][2] = __expf(sc[f][2] - m1); rs1 += sc[f][2];
            sc[f][3] = __expf(sc[f][3] - m1); rs1 += sc[f][3];
        }
        rs0 += __shfl_xor_sync(0xffffffffu, rs0, 1);
        rs0 += __shfl_xor_sync(0xffffffffu, rs0, 2);
        rs1 += __shfl_xor_sync(0xffffffffu, rs1, 1);
        rs1 += __shfl_xor_sync(0xffffffffu, rs1, 2);
        l0 = l0 * c0 + rs0;
        l1 = l1 * c1 + rs1;
#pragma unroll
        for (int n = 0; n < 16; ++n) {
            o[n][0] *= c0; o[n][1] *= c0;
            o[n][2] *= c1; o[n][3] *= c1;
        }

        // ---- pack P into A-fragments (hi + residual lo), in registers ----
        uint32_t pah[4][4], pal[4][4];
#pragma unroll
        for (int kf = 0; kf < 4; ++kf) {
            const int f0 = 2 * kf, f1 = 2 * kf + 1;
            pah[kf][0] = packbf2(sc[f0][0], sc[f0][1]);
            pah[kf][1] = packbf2(sc[f0][2], sc[f0][3]);
            pah[kf][2] = packbf2(sc[f1][0], sc[f1][1]);
            pah[kf][3] = packbf2(sc[f1][2], sc[f1][3]);
            __nv_bfloat162 h0 = *reinterpret_cast<__nv_bfloat162*>(&pah[kf][0]);
            __nv_bfloat162 h1 = *reinterpret_cast<__nv_bfloat162*>(&pah[kf][1]);
            __nv_bfloat162 h2 = *reinterpret_cast<__nv_bfloat162*>(&pah[kf][2]);
            __nv_bfloat162 h3 = *reinterpret_cast<__nv_bfloat162*>(&pah[kf][3]);
            pal[kf][0] = packbf2(sc[f0][0] - __bfloat162float(h0.x),
                                 sc[f0][1] - __bfloat162float(h0.y));
            pal[kf][1] = packbf2(sc[f0][2] - __bfloat162float(h1.x),
                                 sc[f0][3] - __bfloat162float(h1.y));
            pal[kf][2] = packbf2(sc[f1][0] - __bfloat162float(h2.x),
                                 sc[f1][1] - __bfloat162float(h2.y));
            pal[kf][3] = packbf2(sc[f1][2] - __bfloat162float(h3.x),
                                 sc[f1][3] - __bfloat162float(h3.y));
        }

        // ---- O += P V (3-term). kf OUTER, j INNER: 16 independent
        //      accumulator pairs between touches of the same register. ----
#pragma unroll
        for (int kf = 0; kf < 4; ++kf) {
            const int par = kf & 1;
            const uint32_t vch = (uint32_t)((kf >> 1) * 8192);
#pragma unroll
            for (int j = 0; j < 8; ++j) {
                uint32_t vh_f[4], vl_f[4];
                ldm_x4(vh_f, VHb + vch + voff[j][par]);
                ldm_x4(vl_f, VLb + vch + voff[j][par]);
                mma16816(o[2 * j],     pah[kf], &vh_f[0]);
                mma16816(o[2 * j + 1], pah[kf], &vh_f[2]);
                mma16816(o[2 * j],     pal[kf], &vh_f[0]);
                mma16816(o[2 * j + 1], pal[kf], &vh_f[2]);
                mma16816(o[2 * j],     pah[kf], &vl_f[0]);
                mma16816(o[2 * j + 1], pah[kf], &vl_f[2]);
            }
        }
    }

    // ---- epilogue: normalize, split, write attn hi/lo planes ----
    const float inv0 = 1.0f / l0, inv1 = 1.0f / l1;
    const size_t tr0 = (size_t)(b * S_ + qt * 128 + wid * 16 + (lane >> 2));
#pragma unroll
    for (int n = 0; n < 16; ++n) {
        int d = n * 8 + 2 * (lane & 3);
        {
            float v0 = o[n][0] * inv0, v1 = o[n][1] * inv0;
            uint32_t hp = packbf2(v0, v1);
            __nv_bfloat162 hh = *reinterpret_cast<__nv_bfloat162*>(&hp);
            uint32_t lp = packbf2(v0 - __bfloat162float(hh.x),
                                  v1 - __bfloat162float(hh.y));
            size_t idx = tr0 * (NH_ * HD_) + head * HD_ + d;
            *(uint32_t*)&g_at_h[idx] = hp;
            *(uint32_t*)&g_at_l[idx] = lp;
        }
        {
            float v0 = o[n][2] * inv1, v1 = o[n][3] * inv1;
            uint32_t hp = packbf2(v0, v1);
            __nv_bfloat162 hh = *reinterpret_cast<__nv_bfloat162*>(&hp);
            uint32_t lp = packbf2(v0 - __bfloat162float(hh.x),
                                  v1 - __bfloat162float(hh.y));
            size_t idx = (tr0 + 8) * (NH_ * HD_) + head * HD_ + d;
            *(uint32_t*)&g_at_h[idx] = hp;
            *(uint32_t*)&g_at_l[idx] = lp;
        }
    }
#undef FA_LOAD_KV
}

// ---------------------------------------------------------------------------
// Launch: split -> mma GEMMs (QKV) -> rope_split -> v transpose-split ->
// tensor-core FA -> mma GEMM (O). kv_cache append skipped (identity).
// ---------------------------------------------------------------------------
extern "C" void kernel_launch(void* const* d_in, const int* in_sizes, int n_in,
                              void* d_out, int out_size) {
    const float* hs = (const float*)d_in[0];
    const float* wq = (const float*)d_in[1];
    const float* wk = (const float*)d_in[2];
    const float* wv = (const float*)d_in[3];
    const float* wo = (const float*)d_in[4];
    const int* pos  = (const int*)d_in[6];
    float* out = (float*)d_out;

    float *pq, *pk, *pv;
    cudaGetSymbolAddress((void**)&pq, g_q);
    cudaGetSymbolAddress((void**)&pk, g_k);
    cudaGetSymbolAddress((void**)&pv, g_v);

    __nv_bfloat16 *hsh, *hsl, *wqh, *wql, *wkh, *wkl, *wvh, *wvl, *woh, *wol, *ath, *atl;
    cudaGetSymbolAddress((void**)&hsh, g_hs_h); cudaGetSymbolAddress((void**)&hsl, g_hs_l);
    cudaGetSymbolAddress((void**)&wqh, g_wq_h); cudaGetSymbolAddress((void**)&wql, g_wq_l);
    cudaGetSymbolAddress((void**)&wkh, g_wk_h); cudaGetSymbolAddress((void**)&wkl, g_wk_l);
    cudaGetSymbolAddress((void**)&wvh, g_wv_h); cudaGetSymbolAddress((void**)&wvl, g_wv_l);
    cudaGetSymbolAddress((void**)&woh, g_wo_h); cudaGetSymbolAddress((void**)&wol, g_wo_l);
    cudaGetSymbolAddress((void**)&ath, g_at_h); cudaGetSymbolAddress((void**)&atl, g_at_l);

    cudaFuncSetAttribute(gemm_mma_split, cudaFuncAttributeMaxDynamicSharedMemorySize,
                         G_SMEM);
    cudaFuncSetAttribute(fa_mma, cudaFuncAttributeMaxDynamicSharedMemorySize,
                         FA_SMEM);

    const int BIG4 = (NNZ_ * HID_) / 1024;
    const int SML4 = (NKV_ * HD_ * HID_) / 1024;

    // split inputs/weights to bf16 hi/lo planes
    split_fp32_bf16<<<BIG4, 256>>>(hs, hsh, hsl);
    split_fp32_bf16<<<BIG4, 256>>>(wq, wqh, wql);
    split_fp32_bf16<<<SML4, 256>>>(wk, wkh, wkl);
    split_fp32_bf16<<<SML4, 256>>>(wv, wvh, wvl);
    split_fp32_bf16<<<BIG4, 256>>>(wo, woh, wol);

    // QKV projections (tensor cores via mma.sync)
    gemm_mma_split<<<dim3((NH_ * HD_) / 256, NNZ_ / 128), 256, G_SMEM>>>(
        hsh, hsl, wqh, wql, pq, NH_ * HD_, HID_);
    gemm_mma_split<<<dim3((NKV_ * HD_) / 256, NNZ_ / 128), 256, G_SMEM>>>(
        hsh, hsl, wkh, wkl, pk, NKV_ * HD_, HID_);
    gemm_mma_split<<<dim3((NKV_ * HD_) / 256, NNZ_ / 128), 256, G_SMEM>>>(
        hsh, hsl, wvh, wvl, pv, NKV_ * HD_, HID_);

    // RoPE + split (Q scaled), V transpose + split
    rope_split<<<dim3(NNZ_, NH_ + NKV_), 64>>>(pos);
    v_split_t<<<dim3(B_ * NKV_, S_ / 32, HD_ / 32), dim3(32, 8)>>>();

    // Tensor-core causal GQA flash attention -> attn hi/lo planes
    fa_mma<<<dim3(S_ / 128, NH_, B_), 256, FA_SMEM>>>();

    // O projection
    gemm_mma_split<<<dim3(HID_ / 256, NNZ_ / 128), 256, G_SMEM>>>(
        ath, atl, woh, wol, out, HID_, NH_ * HD_);
}